// round 12
// baseline (speedup 1.0000x reference)
#include <cuda_runtime.h>
#include <cstdint>

#define NV_MAX 50000
#define HDIM 64

// -------- scratch (no allocs allowed) --------
__device__ float g_A[NV_MAX * HDIM];
__device__ float g_B[NV_MAX * HDIM];
__device__ float g_P[NV_MAX * HDIM];
__device__ float g_Q[NV_MAX * HDIM];
__device__ float g_aggr[NV_MAX * HDIM];
__device__ float g_aggrp[NV_MAX * HDIM];

typedef unsigned long long ull_t;

__device__ __forceinline__ ull_t pack2(float lo, float hi) {
    ull_t r; asm("mov.b64 %0, {%1, %2};" : "=l"(r) : "f"(lo), "f"(hi)); return r;
}
__device__ __forceinline__ void unpack2(ull_t v, float& lo, float& hi) {
    asm("mov.b64 {%0, %1}, %2;" : "=f"(lo), "=f"(hi) : "l"(v));
}
__device__ __forceinline__ ull_t ffma2(ull_t a, ull_t b, ull_t c) {
    ull_t d; asm("fma.rn.f32x2 %0, %1, %2, %3;" : "=l"(d) : "l"(a), "l"(b), "l"(c)); return d;
}
__device__ __forceinline__ float tanh_f(float x) {
    float y; asm("tanh.approx.f32 %0, %1;" : "=f"(y) : "f"(x)); return y;
}
__device__ __forceinline__ float silu_f(float x) {
    return 0.5f * x * (1.0f + tanh_f(0.5f * x));   // single MUFU
}
__device__ __forceinline__ uint32_t f2tf32(float x) {
    uint32_t r; asm("cvt.rna.tf32.f32 %0, %1;" : "=r"(r) : "f"(x)); return r;
}
__device__ __forceinline__ void mma_tf32(float c[4],
    uint32_t a0, uint32_t a1, uint32_t a2, uint32_t a3, uint32_t b0, uint32_t b1)
{
    asm volatile(
        "mma.sync.aligned.m16n8k8.row.col.f32.tf32.tf32.f32 "
        "{%0,%1,%2,%3}, {%4,%5,%6,%7}, {%8,%9}, {%0,%1,%2,%3};"
        : "+f"(c[0]), "+f"(c[1]), "+f"(c[2]), "+f"(c[3])
        : "r"(a0), "r"(a1), "r"(a2), "r"(a3), "r"(b0), "r"(b1));
}

// ---------------- R9 champion FFMA2 microkernel (pre only) ----------------
#define FFMA2_BLOCK(ha, hb, w)                                              \
    {                                                                       \
        ull_t p0 = pack2(ha.x, ha.x), p1 = pack2(ha.y, ha.y);               \
        ull_t p2 = pack2(ha.z, ha.z), p3 = pack2(ha.w, ha.w);               \
        ull_t p4 = pack2(hb.x, hb.x), p5 = pack2(hb.y, hb.y);               \
        ull_t p6 = pack2(hb.z, hb.z), p7 = pack2(hb.w, hb.w);               \
        acc[0][0] = ffma2(p0, w.x, acc[0][0]); acc[0][1] = ffma2(p0, w.y, acc[0][1]); \
        acc[1][0] = ffma2(p1, w.x, acc[1][0]); acc[1][1] = ffma2(p1, w.y, acc[1][1]); \
        acc[2][0] = ffma2(p2, w.x, acc[2][0]); acc[2][1] = ffma2(p2, w.y, acc[2][1]); \
        acc[3][0] = ffma2(p3, w.x, acc[3][0]); acc[3][1] = ffma2(p3, w.y, acc[3][1]); \
        acc[4][0] = ffma2(p4, w.x, acc[4][0]); acc[4][1] = ffma2(p4, w.y, acc[4][1]); \
        acc[5][0] = ffma2(p5, w.x, acc[5][0]); acc[5][1] = ffma2(p5, w.y, acc[5][1]); \
        acc[6][0] = ffma2(p6, w.x, acc[6][0]); acc[6][1] = ffma2(p6, w.y, acc[6][1]); \
        acc[7][0] = ffma2(p7, w.x, acc[7][0]); acc[7][1] = ffma2(p7, w.y, acc[7][1]); \
    }

template <int K, int ISTRIDE, int WSTRIDE, int HALF>
__device__ __forceinline__ void gemm_8x4(
    const float* __restrict__ inT, const float* __restrict__ W, ull_t acc[8][2])
{
    float4 ha = *(const float4*)(inT);
    float4 hb = *(const float4*)(inT + HALF);
    ulonglong2 w = *(const ulonglong2*)(W);
    #pragma unroll 8
    for (int k = 0; k < K; k++) {
        float4 nha, nhb; ulonglong2 nw;
        if (k + 1 < K) {
            nha = *(const float4*)(inT + (k + 1) * ISTRIDE);
            nhb = *(const float4*)(inT + (k + 1) * ISTRIDE + HALF);
            nw  = *(const ulonglong2*)(W + (k + 1) * WSTRIDE);
        }
        FFMA2_BLOCK(ha, hb, w);
        ha = nha; hb = nhb; w = nw;
    }
}

__device__ __forceinline__ void zero_acc(ull_t acc[8][2]) {
    #pragma unroll
    for (int i = 0; i < 8; i++) { acc[i][0] = 0ULL; acc[i][1] = 0ULL; }
}

// W fragments per-lane in smem: for (kt, nt), lane l holds
// float2( W[8kt+tig][8nt+gid], W[8kt+tig+4][8nt+gid] ), gid=l>>2, tig=l&3.
__device__ __forceinline__ void build_wfrag(
    const float* __restrict__ Wsrc, float* __restrict__ sh_Whi,
    float* __restrict__ sh_Wlo, int tid)
{
    for (int idx = tid; idx < 2048; idx += 256) {
        int kt = idx >> 8;
        int nt = (idx >> 5) & 7;
        int ln = idx & 31;
        int g = ln >> 2, t = ln & 3;
        int r = 8 * kt + t, c = 8 * nt + g;
        float w0 = Wsrc[r * 64 + c];
        float w1 = Wsrc[(r + 4) * 64 + c];
        uint32_t h0 = f2tf32(w0), h1 = f2tf32(w1);
        uint32_t l0 = f2tf32(w0 - __uint_as_float(h0));
        uint32_t l1 = f2tf32(w1 - __uint_as_float(h1));
        sh_Whi[2 * idx]     = __uint_as_float(h0);
        sh_Whi[2 * idx + 1] = __uint_as_float(h1);
        sh_Wlo[2 * idx]     = __uint_as_float(l0);
        sh_Wlo[2 * idx + 1] = __uint_as_float(l1);
    }
}

// Load A fragment (2 rows-of-16 groups, k tile kt) + 3xTF32 split.
__device__ __forceinline__ void load_afrag(
    const float* __restrict__ base, uint32_t ah[4], uint32_t al[4])
{
    float a0f = base[0],       a1f = base[8];
    float a2f = base[4 * 132], a3f = base[4 * 132 + 8];
    ah[0] = f2tf32(a0f); ah[1] = f2tf32(a1f);
    ah[2] = f2tf32(a2f); ah[3] = f2tf32(a3f);
    al[0] = f2tf32(a0f - __uint_as_float(ah[0]));
    al[1] = f2tf32(a1f - __uint_as_float(ah[1]));
    al[2] = f2tf32(a2f - __uint_as_float(ah[2]));
    al[3] = f2tf32(a3f - __uint_as_float(ah[3]));
}

// ============================================================
// Kernel 1 (fused): blockIdx.y==0 -> A,B (+zero aggr); ==1 -> P,Q
// (unchanged R9 champion)
// ============================================================
__global__ void __launch_bounds__(256, 3) pre_kernel(
    const float* __restrict__ x, const float* __restrict__ pe,
    const float* __restrict__ msg_w1, const float* __restrict__ msg_b1,
    const float* __restrict__ mpos_w1, const float* __restrict__ mpos_b1,
    int N)
{
    extern __shared__ float sm[];
    float* sh_inT = sm;                   // [64][68]
    float* sh_W   = sh_inT + 64 * 68;     // [64][128]
    float* sh_b   = sh_W + 64 * 128;      // [128]

    int tid = threadIdx.x;
    int nb = blockIdx.x * 64;
    int tr = tid & 7, tc = tid >> 3;
    int r0 = 4 * tr, c0 = 4 * tc;

    ull_t acc[8][2];
    zero_acc(acc);
    float* dstA;
    float* dstB;

    if (blockIdx.y == 0) {
        if (tid < 128) sh_b[tid] = (tid < 64) ? msg_b1[tid] : 0.0f;
        for (int idx = tid; idx < 2048; idx += 256) {
            int n = idx & 63, s = (idx >> 6) & 15, which = idx >> 10;
            int gn = nb + n;
            if (gn < N) {
                float4* dst = (float4*)((which ? g_aggrp : g_aggr) + (size_t)gn * 64) + s;
                *dst = make_float4(0.f, 0.f, 0.f, 0.f);
            }
        }
        #pragma unroll 1
        for (int ch = 0; ch < 2; ch++) {
            __syncthreads();
            for (int idx = tid; idx < 64 * 128; idx += 256) {
                int k = idx >> 7, c = idx & 127;
                sh_W[idx] = (c < 64) ? msg_w1[(ch * 64 + k) * 64 + c]
                                     : msg_w1[(128 + ch * 64 + k) * 64 + (c - 64)];
            }
            const float* src = (ch == 0) ? x : pe;
            for (int idx = tid; idx < 16 * 64; idx += 256) {
                int n = idx & 63, k4 = idx >> 6;
                int gn = nb + n;
                float4 v = make_float4(0.f, 0.f, 0.f, 0.f);
                if (gn < N) v = *(const float4*)(src + (size_t)gn * 64 + 4 * k4);
                sh_inT[(4 * k4 + 0) * 68 + n] = v.x;
                sh_inT[(4 * k4 + 1) * 68 + n] = v.y;
                sh_inT[(4 * k4 + 2) * 68 + n] = v.z;
                sh_inT[(4 * k4 + 3) * 68 + n] = v.w;
            }
            __syncthreads();
            gemm_8x4<64, 68, 128, 32>(sh_inT + r0, sh_W + c0, acc);
        }
        dstA = g_A; dstB = g_B;
    } else {
        if (tid < 128) sh_b[tid] = (tid < 64) ? mpos_b1[tid] : 0.0f;
        for (int idx = tid; idx < 64 * 128; idx += 256) {
            int k = idx >> 7, c = idx & 127;
            sh_W[idx] = (c < 64) ? mpos_w1[k * 64 + c]
                                 : mpos_w1[(64 + k) * 64 + (c - 64)];
        }
        for (int idx = tid; idx < 16 * 64; idx += 256) {
            int n = idx & 63, k4 = idx >> 6;
            int gn = nb + n;
            float4 v = make_float4(0.f, 0.f, 0.f, 0.f);
            if (gn < N) v = *(const float4*)(pe + (size_t)gn * 64 + 4 * k4);
            sh_inT[(4 * k4 + 0) * 68 + n] = v.x;
            sh_inT[(4 * k4 + 1) * 68 + n] = v.y;
            sh_inT[(4 * k4 + 2) * 68 + n] = v.z;
            sh_inT[(4 * k4 + 3) * 68 + n] = v.w;
        }
        __syncthreads();
        gemm_8x4<64, 68, 128, 32>(sh_inT + r0, sh_W + c0, acc);
        dstA = g_P; dstB = g_Q;
    }

    float* dst = (c0 < 64) ? dstA : dstB;
    int lc = c0 & 63;
    float b0 = sh_b[c0], b1 = sh_b[c0 + 1], b2 = sh_b[c0 + 2], b3 = sh_b[c0 + 3];
    #pragma unroll
    for (int i = 0; i < 8; i++) {
        int rr = (i < 4) ? (r0 + i) : (32 + r0 + i - 4);
        int gn = nb + rr;
        if (gn < N) {
            float o0, o1, o2, o3;
            unpack2(acc[i][0], o0, o1);
            unpack2(acc[i][1], o2, o3);
            *(float4*)(dst + (size_t)gn * 64 + lc) =
                make_float4(o0 + b0, o1 + b1, o2 + b2, o3 + b3);
        }
    }
}

// ============================================================
// Kernel 2: edge kernel — tf32 mma, 2 m-tiles x 4 nt-tiles per warp
// ============================================================
template <bool IS_TANH>
__device__ __forceinline__ void edge_mma_path(
    const float* __restrict__ sh_t, const float* __restrict__ sh_Whi,
    const float* __restrict__ sh_Wlo, const float* __restrict__ bias,
    const int* __restrict__ rec, float* __restrict__ aggr,
    int w, int lane, int eb, int E)
{
    int gid = lane >> 2, tig = lane & 3;
    int mb = (w & 3) * 32;          // 2 m-tiles: edges [mb, mb+16), [mb+16, mb+32)
    int ntb = (w >> 2) * 4;         // 4 nt-tiles: cols [8*ntb, 8*ntb+32)

    float acc[8][4];                // acc[mi*4 + ntl]
    #pragma unroll
    for (int i = 0; i < 8; i++) {
        acc[i][0] = 0.f; acc[i][1] = 0.f; acc[i][2] = 0.f; acc[i][3] = 0.f;
    }

    #pragma unroll 2
    for (int kt = 0; kt < 8; kt++) {
        uint32_t ah[2][4], al[2][4];
        const float* tk = sh_t + (8 * kt + tig) * 132 + mb + gid;
        load_afrag(tk,      ah[0], al[0]);
        load_afrag(tk + 16, ah[1], al[1]);
        #pragma unroll
        for (int ntl = 0; ntl < 4; ntl++) {
            int fo = ((kt * 8 + ntb + ntl) * 32 + lane) * 2;
            float2 bh = *(const float2*)(sh_Whi + fo);
            float2 bl = *(const float2*)(sh_Wlo + fo);
            uint32_t bh0 = __float_as_uint(bh.x), bh1 = __float_as_uint(bh.y);
            uint32_t bl0 = __float_as_uint(bl.x), bl1 = __float_as_uint(bl.y);
            #pragma unroll
            for (int mi = 0; mi < 2; mi++) {
                float* a = acc[mi * 4 + ntl];
                mma_tf32(a, ah[mi][0], ah[mi][1], ah[mi][2], ah[mi][3], bh0, bh1);
                mma_tf32(a, ah[mi][0], ah[mi][1], ah[mi][2], ah[mi][3], bl0, bl1);
                mma_tf32(a, al[mi][0], al[mi][1], al[mi][2], al[mi][3], bh0, bh1);
            }
        }
    }

    #pragma unroll
    for (int mi = 0; mi < 2; mi++) {
        int el0 = mb + 16 * mi + gid, el1 = el0 + 8;
        bool v0 = (eb + el0 < E), v1 = (eb + el1 < E);
        int rc0 = rec[el0], rc1 = rec[el1];
        #pragma unroll
        for (int ntl = 0; ntl < 4; ntl++) {
            int c = 8 * (ntb + ntl) + 2 * tig;
            float b0 = bias[c], b1 = bias[c + 1];
            const float* a = acc[mi * 4 + ntl];
            if (v0) {
                float m0 = a[0] + b0, m1 = a[1] + b1;
                if (IS_TANH) { m0 = tanh_f(m0); m1 = tanh_f(m1); }
                else         { m0 = silu_f(m0); m1 = silu_f(m1); }
                float* dst = aggr + (size_t)rc0 * 64 + c;
                asm volatile("red.global.add.v2.f32 [%0], {%1,%2};"
                             :: "l"(dst), "f"(m0), "f"(m1) : "memory");
            }
            if (v1) {
                float m0 = a[2] + b0, m1 = a[3] + b1;
                if (IS_TANH) { m0 = tanh_f(m0); m1 = tanh_f(m1); }
                else         { m0 = silu_f(m0); m1 = silu_f(m1); }
                float* dst = aggr + (size_t)rc1 * 64 + c;
                asm volatile("red.global.add.v2.f32 [%0], {%1,%2};"
                             :: "l"(dst), "f"(m0), "f"(m1) : "memory");
            }
        }
    }
}

__global__ void __launch_bounds__(256, 3) edge_kernel(
    const float* __restrict__ pos,
    const int* __restrict__ ei,          // int32 (JAX demotes int64)
    const float* __restrict__ msg_w1,
    const float* __restrict__ msg_w2, const float* __restrict__ msg_b2,
    const float* __restrict__ mpos_w1,
    const float* __restrict__ mpos_w2, const float* __restrict__ mpos_b2,
    int E)
{
    extern __shared__ float sm[];
    float* sh_t   = sm;                    // [64][132]
    float* sh_Whi = sh_t + 64 * 132;       // 4096
    float* sh_Wlo = sh_Whi + 4096;         // 4096
    float* sh_we  = sh_Wlo + 4096;         // [64]
    float* sh_ve  = sh_we + 64;
    float* sh_bm  = sh_ve + 64;
    float* sh_bp  = sh_bm + 64;
    int*   sh_rec = (int*)(sh_bp + 64);    // [128]

    int tid = threadIdx.x;
    build_wfrag(msg_w2, sh_Whi, sh_Wlo, tid);
    if (tid < 64) {
        sh_we[tid] = msg_w1[256 * 64 + tid];
        sh_ve[tid] = mpos_w1[128 * 64 + tid];
        sh_bm[tid] = msg_b2[tid];
        sh_bp[tid] = mpos_b2[tid];
    }

    int eb = blockIdx.x * 128;
    int e  = tid & 127;
    int half = tid >> 7;
    int eg = eb + e;
    bool valid = eg < E;
    int snd = 0, rcv = 0;
    if (valid) { snd = ei[eg]; rcv = ei[E + eg]; }
    if (half == 0) sh_rec[e] = rcv;
    float dist = 0.0f;
    if (valid) {
        float dx = pos[snd * 3 + 0] - pos[rcv * 3 + 0];
        float dy = pos[snd * 3 + 1] - pos[rcv * 3 + 1];
        float dz = pos[snd * 3 + 2] - pos[rcv * 3 + 2];
        dist = sqrtf(dx * dx + dy * dy + dz * dz);
    }
    __syncthreads();

    int c0h = half * 32;
    int w = tid >> 5, lane = tid & 31;

    // ---- phase A: silu(A[snd]+B[rcv]+dist*we) -> sh_t, then msg GEMM ----
    {
        const float4* A4 = (const float4*)(g_A + (size_t)snd * 64 + c0h);
        const float4* B4 = (const float4*)(g_B + (size_t)rcv * 64 + c0h);
        const float4* W4 = (const float4*)(sh_we + c0h);
        #pragma unroll
        for (int j = 0; j < 8; j++) {
            float4 a = A4[j], b = B4[j], wv = W4[j];
            float* dst = sh_t + (c0h + 4 * j) * 132 + e;
            dst[0]   = silu_f(a.x + b.x + dist * wv.x);
            dst[132] = silu_f(a.y + b.y + dist * wv.y);
            dst[264] = silu_f(a.z + b.z + dist * wv.z);
            dst[396] = silu_f(a.w + b.w + dist * wv.w);
        }
    }
    __syncthreads();
    edge_mma_path<false>(sh_t, sh_Whi, sh_Wlo, sh_bm, sh_rec, g_aggr, w, lane, eb, E);
    __syncthreads();

    // ---- phase B: rebuild W frags; tanh tile; pos GEMM ----
    build_wfrag(mpos_w2, sh_Whi, sh_Wlo, tid);
    {
        const float4* P4 = (const float4*)(g_P + (size_t)snd * 64 + c0h);
        const float4* Q4 = (const float4*)(g_Q + (size_t)rcv * 64 + c0h);
        const float4* V4 = (const float4*)(sh_ve + c0h);
        #pragma unroll
        for (int j = 0; j < 8; j++) {
            float4 p = P4[j], q = Q4[j], v = V4[j];
            float* dst = sh_t + (c0h + 4 * j) * 132 + e;
            dst[0]   = tanh_f(p.x + q.x + dist * v.x);
            dst[132] = tanh_f(p.y + q.y + dist * v.y);
            dst[264] = tanh_f(p.z + q.z + dist * v.z);
            dst[396] = tanh_f(p.w + q.w + dist * v.w);
        }
    }
    __syncthreads();
    edge_mma_path<true>(sh_t, sh_Whi, sh_Wlo, sh_bp, sh_rec, g_aggrp, w, lane, eb, E);
}

// ============================================================
// Kernel 3 (fused): tf32 mma; blockIdx.y==0 -> update; ==1 -> update_pe
//   128 nodes/CTA; 8 warps x (1 m-tile x 8 nt-tiles) — proven edge mapping.
// ============================================================
__global__ void __launch_bounds__(256, 3) upd_kernel(
    const float* __restrict__ x, const float* __restrict__ pe,
    const float* __restrict__ upd_w1, const float* __restrict__ upd_b1,
    const float* __restrict__ upd_w2, const float* __restrict__ upd_b2,
    const float* __restrict__ upe_w1, const float* __restrict__ upe_b1,
    const float* __restrict__ upe_w2, const float* __restrict__ upe_b2,
    float* __restrict__ out, int N)
{
    extern __shared__ float sm[];
    float* sh_inT = sm;                    // [64][132] (chunk; reused as hT)
    float* sh_Whi = sh_inT + 64 * 132;     // 4096
    float* sh_Wlo = sh_Whi + 4096;         // 4096
    float* sh_b1  = sh_Wlo + 4096;         // [64]
    float* sh_b2  = sh_b1 + 64;            // [64]

    bool is_pe = (blockIdx.y != 0);
    const float* w1 = is_pe ? upe_w1 : upd_w1;
    const float* w2 = is_pe ? upe_w2 : upd_w2;
    int nchunks = is_pe ? 2 : 3;

    int tid = threadIdx.x;
    int nb = blockIdx.x * 128;
    if (tid < 64) {
        sh_b1[tid] = is_pe ? upe_b1[tid] : upd_b1[tid];
        sh_b2[tid] = is_pe ? upe_b2[tid] : upd_b2[tid];
    }

    int w = tid >> 5, lane = tid & 31;
    int gid = lane >> 2, tig = lane & 3;
    int m0 = w * 16;                       // node rows [m0, m0+16)

    float acc[8][4];
    #pragma unroll
    for (int nt = 0; nt < 8; nt++) {
        acc[nt][0] = 0.f; acc[nt][1] = 0.f; acc[nt][2] = 0.f; acc[nt][3] = 0.f;
    }

    // -------- GEMM 1: h = in @ W1, K chunked by 64 --------
    #pragma unroll 1
    for (int ch = 0; ch < nchunks; ch++) {
        __syncthreads();   // previous chunk's frag/inT reads complete
        build_wfrag(w1 + ch * 64 * 64, sh_Whi, sh_Wlo, tid);
        const float* src = is_pe ? ((ch == 0) ? pe : g_aggrp)
                                 : ((ch == 0) ? x : (ch == 1) ? pe : g_aggr);
        for (int idx = tid; idx < 16 * 128; idx += 256) {
            int n = idx & 127, k4 = idx >> 7;
            int gn = nb + n;
            float4 v = make_float4(0.f, 0.f, 0.f, 0.f);
            if (gn < N) v = *(const float4*)(src + (size_t)gn * 64 + 4 * k4);
            sh_inT[(4 * k4 + 0) * 132 + n] = v.x;
            sh_inT[(4 * k4 + 1) * 132 + n] = v.y;
            sh_inT[(4 * k4 + 2) * 132 + n] = v.z;
            sh_inT[(4 * k4 + 3) * 132 + n] = v.w;
        }
        __syncthreads();
        #pragma unroll 2
        for (int kt = 0; kt < 8; kt++) {
            uint32_t ah[4], al[4];
            load_afrag(sh_inT + (8 * kt + tig) * 132 + m0 + gid, ah, al);
            #pragma unroll
            for (int nt = 0; nt < 8; nt++) {
                int fo = ((kt * 8 + nt) * 32 + lane) * 2;
                float2 bh = *(const float2*)(sh_Whi + fo);
                float2 bl = *(const float2*)(sh_Wlo + fo);
                uint32_t bh0 = __float_as_uint(bh.x), bh1 = __float_as_uint(bh.y);
                uint32_t bl0 = __float_as_uint(bl.x), bl1 = __float_as_uint(bl.y);
                mma_tf32(acc[nt], ah[0], ah[1], ah[2], ah[3], bh0, bh1);
                mma_tf32(acc[nt], ah[0], ah[1], ah[2], ah[3], bl0, bl1);
                mma_tf32(acc[nt], al[0], al[1], al[2], al[3], bh0, bh1);
            }
        }
    }

    // -------- activation -> hT (over inT); build W2 frags --------
    __syncthreads();   // all GEMM-1 reads of inT/frags complete
    #pragma unroll
    for (int nt = 0; nt < 8; nt++) {
        int c = 8 * nt + 2 * tig;
        float b0 = sh_b1[c], b1 = sh_b1[c + 1];
        float h00 = acc[nt][0] + b0, h01 = acc[nt][1] + b1;   // row m0+gid
        float h10 = acc[nt][2] + b0, h11 = acc[nt][3] + b1;   // row m0+gid+8
        if (is_pe) { h00 = tanh_f(h00); h01 = tanh_f(h01); h10 = tanh_f(h10); h11 = tanh_f(h11); }
        else       { h00 = silu_f(h00); h01 = silu_f(h01); h10 = silu_f(h10); h11 = silu_f(h11); }
        sh_inT[c * 132 + m0 + gid]           = h00;
        sh_inT[(c + 1) * 132 + m0 + gid]     = h01;
        sh_inT[c * 132 + m0 + gid + 8]       = h10;
        sh_inT[(c + 1) * 132 + m0 + gid + 8] = h11;
    }
    build_wfrag(w2, sh_Whi, sh_Wlo, tid);
    __syncthreads();

    // -------- GEMM 2: out = h @ W2 --------
    float a2[8][4];
    #pragma unroll
    for (int nt = 0; nt < 8; nt++) {
        a2[nt][0] = 0.f; a2[nt][1] = 0.f; a2[nt][2] = 0.f; a2[nt][3] = 0.f;
    }
    #pragma unroll 2
    for (int kt = 0; kt < 8; kt++) {
        uint32_t ah[4], al[4];
        load_afrag(sh_inT + (8 * kt + tig) * 132 + m0 + gid, ah, al);
        #pragma unroll
        for (int nt = 0; nt < 8; nt++) {
            int fo = ((kt * 8 + nt) * 32 + lane) * 2;
            float2 bh = *(const float2*)(sh_Whi + fo);
            float2 bl = *(const float2*)(sh_Wlo + fo);
            uint32_t bh0 = __float_as_uint(bh.x), bh1 = __float_as_uint(bh.y);
            uint32_t bl0 = __float_as_uint(bl.x), bl1 = __float_as_uint(bl.y);
            mma_tf32(a2[nt], ah[0], ah[1], ah[2], ah[3], bh0, bh1);
            mma_tf32(a2[nt], ah[0], ah[1], ah[2], ah[3], bl0, bl1);
            mma_tf32(a2[nt], al[0], al[1], al[2], al[3], bh0, bh1);
        }
    }

    float* obase = out + (is_pe ? (size_t)N * 64 : 0);
    int g0 = nb + m0 + gid, g1 = g0 + 8;
    #pragma unroll
    for (int nt = 0; nt < 8; nt++) {
        int c = 8 * nt + 2 * tig;
        float b0 = sh_b2[c], b1 = sh_b2[c + 1];
        if (g0 < N) {
            float o0 = a2[nt][0] + b0, o1 = a2[nt][1] + b1;
            if (is_pe) { o0 = tanh_f(o0); o1 = tanh_f(o1); }
            *(float2*)(obase + (size_t)g0 * 64 + c) = make_float2(o0, o1);
        }
        if (g1 < N) {
            float o0 = a2[nt][2] + b0, o1 = a2[nt][3] + b1;
            if (is_pe) { o0 = tanh_f(o0); o1 = tanh_f(o1); }
            *(float2*)(obase + (size_t)g1 * 64 + c) = make_float2(o0, o1);
        }
    }
}

// ============================================================
// Host launch
// ============================================================
extern "C" void kernel_launch(void* const* d_in, const int* in_sizes, int n_in,
                              void* d_out, int out_size)
{
    const float* x       = (const float*)d_in[0];
    const float* pos     = (const float*)d_in[1];
    const float* pe      = (const float*)d_in[2];
    const int*   ei      = (const int*)d_in[3];
    const float* msg_w1  = (const float*)d_in[4];
    const float* msg_b1  = (const float*)d_in[5];
    const float* msg_w2  = (const float*)d_in[6];
    const float* msg_b2  = (const float*)d_in[7];
    const float* mpos_w1 = (const float*)d_in[8];
    const float* mpos_b1 = (const float*)d_in[9];
    const float* mpos_w2 = (const float*)d_in[10];
    const float* mpos_b2 = (const float*)d_in[11];
    const float* upd_w1  = (const float*)d_in[12];
    const float* upd_b1  = (const float*)d_in[13];
    const float* upd_w2  = (const float*)d_in[14];
    const float* upd_b2  = (const float*)d_in[15];
    const float* upe_w1  = (const float*)d_in[16];
    const float* upe_b1  = (const float*)d_in[17];
    const float* upe_w2  = (const float*)d_in[18];
    const float* upe_b2  = (const float*)d_in[19];

    int N = in_sizes[0] / 64;
    int E = in_sizes[3] / 2;

    const int SMEM_PRE  = (64 * 68 + 64 * 128 + 128) * 4;                  // 50,688 B
    const int SMEM_EDGE = (64 * 132 + 4096 + 4096 + 256) * 4 + 512;        // 68,096 B
    const int SMEM_UPD  = (64 * 132 + 4096 + 4096 + 128) * 4;              // 67,072 B

    cudaFuncSetAttribute(pre_kernel,  cudaFuncAttributeMaxDynamicSharedMemorySize, SMEM_PRE);
    cudaFuncSetAttribute(edge_kernel, cudaFuncAttributeMaxDynamicSharedMemorySize, SMEM_EDGE);
    cudaFuncSetAttribute(upd_kernel,  cudaFuncAttributeMaxDynamicSharedMemorySize, SMEM_UPD);

    dim3 gpre((N + 63) / 64, 2);
    dim3 gupd((N + 127) / 128, 2);
    pre_kernel<<<gpre, 256, SMEM_PRE>>>(x, pe, msg_w1, msg_b1, mpos_w1, mpos_b1, N);
    edge_kernel<<<(E + 127) / 128, 256, SMEM_EDGE>>>(pos, ei, msg_w1, msg_w2, msg_b2,
                                                     mpos_w1, mpos_w2, mpos_b2, E);
    upd_kernel<<<gupd, 256, SMEM_UPD>>>(x, pe, upd_w1, upd_b1, upd_w2, upd_b2,
                                        upe_w1, upe_b1, upe_w2, upe_b2,
                                        (float*)d_out, N);
}

// round 13
// speedup vs baseline: 1.0945x; 1.0945x over previous
#include <cuda_runtime.h>
#include <cstdint>

#define NV_MAX 50000
#define HDIM 64

// -------- scratch (no allocs allowed) --------
__device__ float g_A[NV_MAX * HDIM];
__device__ float g_B[NV_MAX * HDIM];
__device__ float g_P[NV_MAX * HDIM];
__device__ float g_Q[NV_MAX * HDIM];
__device__ float g_aggr[NV_MAX * HDIM];
__device__ float g_aggrp[NV_MAX * HDIM];
// precomputed tf32 W fragments (hi[4096] ++ lo[4096] each)
__device__ float g_fragM[8192];
__device__ float g_fragP[8192];

typedef unsigned long long ull_t;

__device__ __forceinline__ ull_t pack2(float lo, float hi) {
    ull_t r; asm("mov.b64 %0, {%1, %2};" : "=l"(r) : "f"(lo), "f"(hi)); return r;
}
__device__ __forceinline__ void unpack2(ull_t v, float& lo, float& hi) {
    asm("mov.b64 {%0, %1}, %2;" : "=f"(lo), "=f"(hi) : "l"(v));
}
__device__ __forceinline__ ull_t ffma2(ull_t a, ull_t b, ull_t c) {
    ull_t d; asm("fma.rn.f32x2 %0, %1, %2, %3;" : "=l"(d) : "l"(a), "l"(b), "l"(c)); return d;
}
__device__ __forceinline__ float tanh_f(float x) {
    float y; asm("tanh.approx.f32 %0, %1;" : "=f"(y) : "f"(x)); return y;
}
__device__ __forceinline__ float silu_f(float x) {
    return 0.5f * x * (1.0f + tanh_f(0.5f * x));   // single MUFU
}
__device__ __forceinline__ uint32_t f2tf32(float x) {
    uint32_t r; asm("cvt.rna.tf32.f32 %0, %1;" : "=r"(r) : "f"(x)); return r;
}
__device__ __forceinline__ void mma_tf32(float c[4],
    uint32_t a0, uint32_t a1, uint32_t a2, uint32_t a3, uint32_t b0, uint32_t b1)
{
    asm volatile(
        "mma.sync.aligned.m16n8k8.row.col.f32.tf32.tf32.f32 "
        "{%0,%1,%2,%3}, {%4,%5,%6,%7}, {%8,%9}, {%0,%1,%2,%3};"
        : "+f"(c[0]), "+f"(c[1]), "+f"(c[2]), "+f"(c[3])
        : "r"(a0), "r"(a1), "r"(a2), "r"(a3), "r"(b0), "r"(b1));
}

// ---------------- R9 champion FFMA2 microkernel (pre/upd) ----------------
#define FFMA2_BLOCK(ha, hb, w)                                              \
    {                                                                       \
        ull_t p0 = pack2(ha.x, ha.x), p1 = pack2(ha.y, ha.y);               \
        ull_t p2 = pack2(ha.z, ha.z), p3 = pack2(ha.w, ha.w);               \
        ull_t p4 = pack2(hb.x, hb.x), p5 = pack2(hb.y, hb.y);               \
        ull_t p6 = pack2(hb.z, hb.z), p7 = pack2(hb.w, hb.w);               \
        acc[0][0] = ffma2(p0, w.x, acc[0][0]); acc[0][1] = ffma2(p0, w.y, acc[0][1]); \
        acc[1][0] = ffma2(p1, w.x, acc[1][0]); acc[1][1] = ffma2(p1, w.y, acc[1][1]); \
        acc[2][0] = ffma2(p2, w.x, acc[2][0]); acc[2][1] = ffma2(p2, w.y, acc[2][1]); \
        acc[3][0] = ffma2(p3, w.x, acc[3][0]); acc[3][1] = ffma2(p3, w.y, acc[3][1]); \
        acc[4][0] = ffma2(p4, w.x, acc[4][0]); acc[4][1] = ffma2(p4, w.y, acc[4][1]); \
        acc[5][0] = ffma2(p5, w.x, acc[5][0]); acc[5][1] = ffma2(p5, w.y, acc[5][1]); \
        acc[6][0] = ffma2(p6, w.x, acc[6][0]); acc[6][1] = ffma2(p6, w.y, acc[6][1]); \
        acc[7][0] = ffma2(p7, w.x, acc[7][0]); acc[7][1] = ffma2(p7, w.y, acc[7][1]); \
    }

template <int K, int ISTRIDE, int WSTRIDE, int HALF>
__device__ __forceinline__ void gemm_8x4(
    const float* __restrict__ inT, const float* __restrict__ W, ull_t acc[8][2])
{
    float4 ha = *(const float4*)(inT);
    float4 hb = *(const float4*)(inT + HALF);
    ulonglong2 w = *(const ulonglong2*)(W);
    #pragma unroll 8
    for (int k = 0; k < K; k++) {
        float4 nha, nhb; ulonglong2 nw;
        if (k + 1 < K) {
            nha = *(const float4*)(inT + (k + 1) * ISTRIDE);
            nhb = *(const float4*)(inT + (k + 1) * ISTRIDE + HALF);
            nw  = *(const ulonglong2*)(W + (k + 1) * WSTRIDE);
        }
        FFMA2_BLOCK(ha, hb, w);
        ha = nha; hb = nhb; w = nw;
    }
}

__device__ __forceinline__ void zero_acc(ull_t acc[8][2]) {
    #pragma unroll
    for (int i = 0; i < 8; i++) { acc[i][0] = 0ULL; acc[i][1] = 0ULL; }
}

// ============================================================
// Kernel 0: one-CTA W-fragment precompute (both edge paths)
//   layout per path: [0..4095]=hi frags, [4096..8191]=lo frags,
//   frag (kt,nt) lane l: float2( W[8kt+tig][8nt+gid], W[8kt+tig+4][8nt+gid] )
// ============================================================
__global__ void wfrag_kernel(const float* __restrict__ msg_w2,
                             const float* __restrict__ mpos_w2)
{
    int tid = threadIdx.x;
    for (int idx = tid; idx < 2048; idx += 256) {
        int kt = idx >> 8;
        int nt = (idx >> 5) & 7;
        int ln = idx & 31;
        int g = ln >> 2, t = ln & 3;
        int r = 8 * kt + t, c = 8 * nt + g;

        float w0 = msg_w2[r * 64 + c];
        float w1 = msg_w2[(r + 4) * 64 + c];
        uint32_t h0 = f2tf32(w0), h1 = f2tf32(w1);
        g_fragM[2 * idx]            = __uint_as_float(h0);
        g_fragM[2 * idx + 1]        = __uint_as_float(h1);
        g_fragM[4096 + 2 * idx]     = __uint_as_float(f2tf32(w0 - __uint_as_float(h0)));
        g_fragM[4096 + 2 * idx + 1] = __uint_as_float(f2tf32(w1 - __uint_as_float(h1)));

        w0 = mpos_w2[r * 64 + c];
        w1 = mpos_w2[(r + 4) * 64 + c];
        h0 = f2tf32(w0); h1 = f2tf32(w1);
        g_fragP[2 * idx]            = __uint_as_float(h0);
        g_fragP[2 * idx + 1]        = __uint_as_float(h1);
        g_fragP[4096 + 2 * idx]     = __uint_as_float(f2tf32(w0 - __uint_as_float(h0)));
        g_fragP[4096 + 2 * idx + 1] = __uint_as_float(f2tf32(w1 - __uint_as_float(h1)));
    }
}

// ============================================================
// Kernel 1 (fused): blockIdx.y==0 -> A,B (+zero aggr); ==1 -> P,Q
// (unchanged R11 champion)
// ============================================================
__global__ void __launch_bounds__(256, 3) pre_kernel(
    const float* __restrict__ x, const float* __restrict__ pe,
    const float* __restrict__ msg_w1, const float* __restrict__ msg_b1,
    const float* __restrict__ mpos_w1, const float* __restrict__ mpos_b1,
    int N)
{
    extern __shared__ float sm[];
    float* sh_inT = sm;                   // [64][68]
    float* sh_W   = sh_inT + 64 * 68;     // [64][128]
    float* sh_b   = sh_W + 64 * 128;      // [128]

    int tid = threadIdx.x;
    int nb = blockIdx.x * 64;
    int tr = tid & 7, tc = tid >> 3;
    int r0 = 4 * tr, c0 = 4 * tc;

    ull_t acc[8][2];
    zero_acc(acc);
    float* dstA;
    float* dstB;

    if (blockIdx.y == 0) {
        if (tid < 128) sh_b[tid] = (tid < 64) ? msg_b1[tid] : 0.0f;
        for (int idx = tid; idx < 2048; idx += 256) {
            int n = idx & 63, s = (idx >> 6) & 15, which = idx >> 10;
            int gn = nb + n;
            if (gn < N) {
                float4* dst = (float4*)((which ? g_aggrp : g_aggr) + (size_t)gn * 64) + s;
                *dst = make_float4(0.f, 0.f, 0.f, 0.f);
            }
        }
        #pragma unroll 1
        for (int ch = 0; ch < 2; ch++) {
            __syncthreads();
            for (int idx = tid; idx < 64 * 128; idx += 256) {
                int k = idx >> 7, c = idx & 127;
                sh_W[idx] = (c < 64) ? msg_w1[(ch * 64 + k) * 64 + c]
                                     : msg_w1[(128 + ch * 64 + k) * 64 + (c - 64)];
            }
            const float* src = (ch == 0) ? x : pe;
            for (int idx = tid; idx < 16 * 64; idx += 256) {
                int n = idx & 63, k4 = idx >> 6;
                int gn = nb + n;
                float4 v = make_float4(0.f, 0.f, 0.f, 0.f);
                if (gn < N) v = *(const float4*)(src + (size_t)gn * 64 + 4 * k4);
                sh_inT[(4 * k4 + 0) * 68 + n] = v.x;
                sh_inT[(4 * k4 + 1) * 68 + n] = v.y;
                sh_inT[(4 * k4 + 2) * 68 + n] = v.z;
                sh_inT[(4 * k4 + 3) * 68 + n] = v.w;
            }
            __syncthreads();
            gemm_8x4<64, 68, 128, 32>(sh_inT + r0, sh_W + c0, acc);
        }
        dstA = g_A; dstB = g_B;
    } else {
        if (tid < 128) sh_b[tid] = (tid < 64) ? mpos_b1[tid] : 0.0f;
        for (int idx = tid; idx < 64 * 128; idx += 256) {
            int k = idx >> 7, c = idx & 127;
            sh_W[idx] = (c < 64) ? mpos_w1[k * 64 + c]
                                 : mpos_w1[(64 + k) * 64 + (c - 64)];
        }
        for (int idx = tid; idx < 16 * 64; idx += 256) {
            int n = idx & 63, k4 = idx >> 6;
            int gn = nb + n;
            float4 v = make_float4(0.f, 0.f, 0.f, 0.f);
            if (gn < N) v = *(const float4*)(pe + (size_t)gn * 64 + 4 * k4);
            sh_inT[(4 * k4 + 0) * 68 + n] = v.x;
            sh_inT[(4 * k4 + 1) * 68 + n] = v.y;
            sh_inT[(4 * k4 + 2) * 68 + n] = v.z;
            sh_inT[(4 * k4 + 3) * 68 + n] = v.w;
        }
        __syncthreads();
        gemm_8x4<64, 68, 128, 32>(sh_inT + r0, sh_W + c0, acc);
        dstA = g_P; dstB = g_Q;
    }

    float* dst = (c0 < 64) ? dstA : dstB;
    int lc = c0 & 63;
    float b0 = sh_b[c0], b1 = sh_b[c0 + 1], b2 = sh_b[c0 + 2], b3 = sh_b[c0 + 3];
    #pragma unroll
    for (int i = 0; i < 8; i++) {
        int rr = (i < 4) ? (r0 + i) : (32 + r0 + i - 4);
        int gn = nb + rr;
        if (gn < N) {
            float o0, o1, o2, o3;
            unpack2(acc[i][0], o0, o1);
            unpack2(acc[i][1], o2, o3);
            *(float4*)(dst + (size_t)gn * 64 + lc) =
                make_float4(o0 + b0, o1 + b1, o2 + b2, o3 + b3);
        }
    }
}

// ============================================================
// Kernel 2: edge kernel — tf32 mma (R11 mapping), frags copied from global
// ============================================================
template <bool IS_TANH>
__device__ __forceinline__ void edge_mma_path(
    const float* __restrict__ sh_t, const float* __restrict__ sh_Whi,
    const float* __restrict__ sh_Wlo, const float* __restrict__ bias,
    const int* __restrict__ rec, float* __restrict__ aggr,
    int w, int lane, int eb, int E)
{
    int gid = lane >> 2, tig = lane & 3;
    int e0 = w * 16;

    float acc[8][4];
    #pragma unroll
    for (int nt = 0; nt < 8; nt++) {
        acc[nt][0] = 0.f; acc[nt][1] = 0.f; acc[nt][2] = 0.f; acc[nt][3] = 0.f;
    }

    #pragma unroll 2
    for (int kt = 0; kt < 8; kt++) {
        const float* tk = sh_t + (8 * kt + tig) * 132 + e0 + gid;
        float a0f = tk[0],       a1f = tk[8];
        float a2f = tk[4 * 132], a3f = tk[4 * 132 + 8];
        uint32_t a0h = f2tf32(a0f), a1h = f2tf32(a1f);
        uint32_t a2h = f2tf32(a2f), a3h = f2tf32(a3f);
        uint32_t a0l = f2tf32(a0f - __uint_as_float(a0h));
        uint32_t a1l = f2tf32(a1f - __uint_as_float(a1h));
        uint32_t a2l = f2tf32(a2f - __uint_as_float(a2h));
        uint32_t a3l = f2tf32(a3f - __uint_as_float(a3h));
        #pragma unroll
        for (int nt = 0; nt < 8; nt++) {
            int fo = ((kt * 8 + nt) * 32 + lane) * 2;
            float2 bh = *(const float2*)(sh_Whi + fo);
            float2 bl = *(const float2*)(sh_Wlo + fo);
            uint32_t bh0 = __float_as_uint(bh.x), bh1 = __float_as_uint(bh.y);
            uint32_t bl0 = __float_as_uint(bl.x), bl1 = __float_as_uint(bl.y);
            mma_tf32(acc[nt], a0h, a1h, a2h, a3h, bh0, bh1);
            mma_tf32(acc[nt], a0h, a1h, a2h, a3h, bl0, bl1);
            mma_tf32(acc[nt], a0l, a1l, a2l, a3l, bh0, bh1);
        }
    }

    int el0 = e0 + gid, el1 = el0 + 8;
    bool v0 = (eb + el0 < E), v1 = (eb + el1 < E);
    int rc0 = rec[el0], rc1 = rec[el1];
    #pragma unroll
    for (int nt = 0; nt < 8; nt++) {
        int c = 8 * nt + 2 * tig;
        float b0 = bias[c], b1 = bias[c + 1];
        if (v0) {
            float m0 = acc[nt][0] + b0, m1 = acc[nt][1] + b1;
            if (IS_TANH) { m0 = tanh_f(m0); m1 = tanh_f(m1); }
            else         { m0 = silu_f(m0); m1 = silu_f(m1); }
            float* dst = aggr + (size_t)rc0 * 64 + c;
            asm volatile("red.global.add.v2.f32 [%0], {%1,%2};"
                         :: "l"(dst), "f"(m0), "f"(m1) : "memory");
        }
        if (v1) {
            float m0 = acc[nt][2] + b0, m1 = acc[nt][3] + b1;
            if (IS_TANH) { m0 = tanh_f(m0); m1 = tanh_f(m1); }
            else         { m0 = silu_f(m0); m1 = silu_f(m1); }
            float* dst = aggr + (size_t)rc1 * 64 + c;
            asm volatile("red.global.add.v2.f32 [%0], {%1,%2};"
                         :: "l"(dst), "f"(m0), "f"(m1) : "memory");
        }
    }
}

__global__ void __launch_bounds__(256, 3) edge_kernel(
    const float* __restrict__ pos,
    const int* __restrict__ ei,          // int32 (JAX demotes int64)
    const float* __restrict__ msg_w1,
    const float* __restrict__ msg_b2,
    const float* __restrict__ mpos_w1,
    const float* __restrict__ mpos_b2,
    int E)
{
    extern __shared__ float sm[];
    float* sh_t   = sm;                    // [64][132]
    float* sh_Whi = sh_t + 64 * 132;       // 4096 (hi; lo follows contiguously)
    float* sh_Wlo = sh_Whi + 4096;         // 4096
    float* sh_we  = sh_Wlo + 4096;         // [64]
    float* sh_ve  = sh_we + 64;
    float* sh_bm  = sh_ve + 64;
    float* sh_bp  = sh_bm + 64;
    int*   sh_rec = (int*)(sh_bp + 64);    // [128]

    int tid = threadIdx.x;
    // coalesced copy of precomputed msg frags (hi+lo = 8192 floats)
    {
        const float4* src = (const float4*)g_fragM;
        float4* dst = (float4*)sh_Whi;
        #pragma unroll
        for (int i = 0; i < 8; i++) dst[tid + 256 * i] = src[tid + 256 * i];
    }
    if (tid < 64) {
        sh_we[tid] = msg_w1[256 * 64 + tid];
        sh_ve[tid] = mpos_w1[128 * 64 + tid];
        sh_bm[tid] = msg_b2[tid];
        sh_bp[tid] = mpos_b2[tid];
    }

    int eb = blockIdx.x * 128;
    int e  = tid & 127;
    int half = tid >> 7;
    int eg = eb + e;
    bool valid = eg < E;
    int snd = 0, rcv = 0;
    if (valid) { snd = ei[eg]; rcv = ei[E + eg]; }
    if (half == 0) sh_rec[e] = rcv;
    float dist = 0.0f;
    if (valid) {
        float dx = pos[snd * 3 + 0] - pos[rcv * 3 + 0];
        float dy = pos[snd * 3 + 1] - pos[rcv * 3 + 1];
        float dz = pos[snd * 3 + 2] - pos[rcv * 3 + 2];
        dist = sqrtf(dx * dx + dy * dy + dz * dz);
    }
    __syncthreads();

    int c0h = half * 32;
    int w = tid >> 5, lane = tid & 31;

    // ---- phase A: silu(A[snd]+B[rcv]+dist*we) -> sh_t, then msg GEMM ----
    {
        const float4* A4 = (const float4*)(g_A + (size_t)snd * 64 + c0h);
        const float4* B4 = (const float4*)(g_B + (size_t)rcv * 64 + c0h);
        const float4* W4 = (const float4*)(sh_we + c0h);
        #pragma unroll
        for (int j = 0; j < 8; j++) {
            float4 a = A4[j], b = B4[j], wv = W4[j];
            float* dst = sh_t + (c0h + 4 * j) * 132 + e;
            dst[0]   = silu_f(a.x + b.x + dist * wv.x);
            dst[132] = silu_f(a.y + b.y + dist * wv.y);
            dst[264] = silu_f(a.z + b.z + dist * wv.z);
            dst[396] = silu_f(a.w + b.w + dist * wv.w);
        }
    }
    __syncthreads();
    edge_mma_path<false>(sh_t, sh_Whi, sh_Wlo, sh_bm, sh_rec, g_aggr, w, lane, eb, E);
    __syncthreads();   // all reads of sh_t / frags complete

    // ---- phase B: copy pos frags; tanh tile; pos GEMM ----
    {
        const float4* src = (const float4*)g_fragP;
        float4* dst = (float4*)sh_Whi;
        #pragma unroll
        for (int i = 0; i < 8; i++) dst[tid + 256 * i] = src[tid + 256 * i];
    }
    {
        const float4* P4 = (const float4*)(g_P + (size_t)snd * 64 + c0h);
        const float4* Q4 = (const float4*)(g_Q + (size_t)rcv * 64 + c0h);
        const float4* V4 = (const float4*)(sh_ve + c0h);
        #pragma unroll
        for (int j = 0; j < 8; j++) {
            float4 p = P4[j], q = Q4[j], v = V4[j];
            float* dst = sh_t + (c0h + 4 * j) * 132 + e;
            dst[0]   = tanh_f(p.x + q.x + dist * v.x);
            dst[132] = tanh_f(p.y + q.y + dist * v.y);
            dst[264] = tanh_f(p.z + q.z + dist * v.z);
            dst[396] = tanh_f(p.w + q.w + dist * v.w);
        }
    }
    __syncthreads();
    edge_mma_path<true>(sh_t, sh_Whi, sh_Wlo, sh_bp, sh_rec, g_aggrp, w, lane, eb, E);
}

// ============================================================
// Kernel 3 (fused): blockIdx.y==0 -> update; ==1 -> update_pe
// (unchanged R11 champion, FFMA2)
// ============================================================
__global__ void __launch_bounds__(256, 3) upd_kernel(
    const float* __restrict__ x, const float* __restrict__ pe,
    const float* __restrict__ upd_w1, const float* __restrict__ upd_b1,
    const float* __restrict__ upd_w2, const float* __restrict__ upd_b2,
    const float* __restrict__ upe_w1, const float* __restrict__ upe_b1,
    const float* __restrict__ upe_w2, const float* __restrict__ upe_b2,
    float* __restrict__ out, int N)
{
    extern __shared__ float sm[];
    float* sh_inT = sm;                    // [64][132]
    float* sh_Wc  = sh_inT + 64 * 132;     // [64][64]
    float* sh_b1  = sh_Wc + 64 * 64;       // [64]
    float* sh_b2  = sh_b1 + 64;            // [64]

    bool is_pe = (blockIdx.y != 0);
    const float* w1 = is_pe ? upe_w1 : upd_w1;
    const float* w2 = is_pe ? upe_w2 : upd_w2;
    int nchunks = is_pe ? 2 : 3;

    int tid = threadIdx.x;
    int nb = blockIdx.x * 128;
    if (tid < 64) {
        sh_b1[tid] = is_pe ? upe_b1[tid] : upd_b1[tid];
        sh_b2[tid] = is_pe ? upe_b2[tid] : upd_b2[tid];
    }

    int tr = tid & 15, tc = tid >> 4;
    int r0 = 4 * tr, c0 = 4 * tc;

    ull_t acc[8][2];
    zero_acc(acc);

    #pragma unroll 1
    for (int ch = 0; ch < nchunks; ch++) {
        __syncthreads();
        for (int idx = tid; idx < 64 * 64; idx += 256)
            sh_Wc[idx] = w1[ch * 64 * 64 + idx];
        const float* src = is_pe ? ((ch == 0) ? pe : g_aggrp)
                                 : ((ch == 0) ? x : (ch == 1) ? pe : g_aggr);
        for (int idx = tid; idx < 16 * 128; idx += 256) {
            int n = idx & 127, k4 = idx >> 7;
            int gn = nb + n;
            float4 v = make_float4(0.f, 0.f, 0.f, 0.f);
            if (gn < N) v = *(const float4*)(src + (size_t)gn * 64 + 4 * k4);
            sh_inT[(4 * k4 + 0) * 132 + n] = v.x;
            sh_inT[(4 * k4 + 1) * 132 + n] = v.y;
            sh_inT[(4 * k4 + 2) * 132 + n] = v.z;
            sh_inT[(4 * k4 + 3) * 132 + n] = v.w;
        }
        __syncthreads();
        gemm_8x4<64, 132, 64, 64>(sh_inT + r0, sh_Wc + c0, acc);
    }

    __syncthreads();
    #pragma unroll
    for (int j = 0; j < 2; j++) {
        float bj0 = sh_b1[c0 + 2 * j], bj1 = sh_b1[c0 + 2 * j + 1];
        float lo[8], hi[8];
        #pragma unroll
        for (int i = 0; i < 8; i++) { unpack2(acc[i][j], lo[i], hi[i]); }
        #pragma unroll
        for (int i = 0; i < 8; i++) {
            lo[i] = is_pe ? tanh_f(lo[i] + bj0) : silu_f(lo[i] + bj0);
            hi[i] = is_pe ? tanh_f(hi[i] + bj1) : silu_f(hi[i] + bj1);
        }
        float* d0 = sh_inT + (c0 + 2 * j) * 132;
        float* d1 = d0 + 132;
        *(float4*)(d0 + r0)      = make_float4(lo[0], lo[1], lo[2], lo[3]);
        *(float4*)(d0 + 64 + r0) = make_float4(lo[4], lo[5], lo[6], lo[7]);
        *(float4*)(d1 + r0)      = make_float4(hi[0], hi[1], hi[2], hi[3]);
        *(float4*)(d1 + 64 + r0) = make_float4(hi[4], hi[5], hi[6], hi[7]);
    }
    for (int idx = tid; idx < 64 * 64; idx += 256) sh_Wc[idx] = w2[idx];
    __syncthreads();

    ull_t a2[8][2];
    zero_acc(a2);
    gemm_8x4<64, 132, 64, 64>(sh_inT + r0, sh_Wc + c0, a2);

    float b0 = sh_b2[c0], b1 = sh_b2[c0 + 1], b2 = sh_b2[c0 + 2], b3 = sh_b2[c0 + 3];
    float* obase = out + (is_pe ? (size_t)N * 64 : 0);
    #pragma unroll
    for (int i = 0; i < 8; i++) {
        int rr = (i < 4) ? (r0 + i) : (64 + r0 + i - 4);
        int g = nb + rr;
        if (g < N) {
            float o0, o1, o2, o3;
            unpack2(a2[i][0], o0, o1);
            unpack2(a2[i][1], o2, o3);
            if (is_pe) { o0 = tanh_f(o0 + b0); o1 = tanh_f(o1 + b1);
                         o2 = tanh_f(o2 + b2); o3 = tanh_f(o3 + b3); }
            else       { o0 += b0; o1 += b1; o2 += b2; o3 += b3; }
            *(float4*)(obase + (size_t)g * 64 + c0) = make_float4(o0, o1, o2, o3);
        }
    }
}

// ============================================================
// Host launch
// ============================================================
extern "C" void kernel_launch(void* const* d_in, const int* in_sizes, int n_in,
                              void* d_out, int out_size)
{
    const float* x       = (const float*)d_in[0];
    const float* pos     = (const float*)d_in[1];
    const float* pe      = (const float*)d_in[2];
    const int*   ei      = (const int*)d_in[3];
    const float* msg_w1  = (const float*)d_in[4];
    const float* msg_b1  = (const float*)d_in[5];
    const float* msg_w2  = (const float*)d_in[6];
    const float* msg_b2  = (const float*)d_in[7];
    const float* mpos_w1 = (const float*)d_in[8];
    const float* mpos_b1 = (const float*)d_in[9];
    const float* mpos_w2 = (const float*)d_in[10];
    const float* mpos_b2 = (const float*)d_in[11];
    const float* upd_w1  = (const float*)d_in[12];
    const float* upd_b1  = (const float*)d_in[13];
    const float* upd_w2  = (const float*)d_in[14];
    const float* upd_b2  = (const float*)d_in[15];
    const float* upe_w1  = (const float*)d_in[16];
    const float* upe_b1  = (const float*)d_in[17];
    const float* upe_w2  = (const float*)d_in[18];
    const float* upe_b2  = (const float*)d_in[19];

    int N = in_sizes[0] / 64;
    int E = in_sizes[3] / 2;

    const int SMEM_PRE  = (64 * 68 + 64 * 128 + 128) * 4;                  // 50,688 B
    const int SMEM_EDGE = (64 * 132 + 4096 + 4096 + 256) * 4 + 512;        // 68,096 B
    const int SMEM_UPD  = (64 * 132 + 64 * 64 + 128) * 4;                  // 50,688 B

    cudaFuncSetAttribute(pre_kernel,  cudaFuncAttributeMaxDynamicSharedMemorySize, SMEM_PRE);
    cudaFuncSetAttribute(edge_kernel, cudaFuncAttributeMaxDynamicSharedMemorySize, SMEM_EDGE);
    cudaFuncSetAttribute(upd_kernel,  cudaFuncAttributeMaxDynamicSharedMemorySize, SMEM_UPD);

    dim3 gpre((N + 63) / 64, 2);
    dim3 gupd((N + 127) / 128, 2);
    wfrag_kernel<<<1, 256>>>(msg_w2, mpos_w2);
    pre_kernel<<<gpre, 256, SMEM_PRE>>>(x, pe, msg_w1, msg_b1, mpos_w1, mpos_b1, N);
    edge_kernel<<<(E + 127) / 128, 256, SMEM_EDGE>>>(pos, ei, msg_w1, msg_b2,
                                                     mpos_w1, mpos_b2, E);
    upd_kernel<<<gupd, 256, SMEM_UPD>>>(x, pe, upd_w1, upd_b1, upd_w2, upd_b2,
                                        upe_w1, upe_b1, upe_w2, upe_b2,
                                        (float*)d_out, N);
}

// round 14
// speedup vs baseline: 1.1262x; 1.0289x over previous
#include <cuda_runtime.h>
#include <cstdint>

#define NV_MAX 50000
#define HDIM 64

// -------- scratch (no allocs allowed) --------
__device__ float g_A[NV_MAX * HDIM];
__device__ float g_B[NV_MAX * HDIM];
__device__ float g_P[NV_MAX * HDIM];
__device__ float g_Q[NV_MAX * HDIM];
__device__ float g_aggr[NV_MAX * HDIM];
__device__ float g_aggrp[NV_MAX * HDIM];
// precomputed tf32 W fragments (hi[4096] ++ lo[4096] per set)
__device__ float g_fragM[8192];            // msg_w2
__device__ float g_fragP[8192];            // mpos_w2
__device__ float g_fragUpd[4 * 8192];      // upd_w1 ch0..2, upd_w2
__device__ float g_fragUpe[3 * 8192];      // upe_w1 ch0..1, upe_w2

typedef unsigned long long ull_t;

__device__ __forceinline__ ull_t pack2(float lo, float hi) {
    ull_t r; asm("mov.b64 %0, {%1, %2};" : "=l"(r) : "f"(lo), "f"(hi)); return r;
}
__device__ __forceinline__ void unpack2(ull_t v, float& lo, float& hi) {
    asm("mov.b64 {%0, %1}, %2;" : "=f"(lo), "=f"(hi) : "l"(v));
}
__device__ __forceinline__ ull_t ffma2(ull_t a, ull_t b, ull_t c) {
    ull_t d; asm("fma.rn.f32x2 %0, %1, %2, %3;" : "=l"(d) : "l"(a), "l"(b), "l"(c)); return d;
}
__device__ __forceinline__ float tanh_f(float x) {
    float y; asm("tanh.approx.f32 %0, %1;" : "=f"(y) : "f"(x)); return y;
}
__device__ __forceinline__ float silu_f(float x) {
    return 0.5f * x * (1.0f + tanh_f(0.5f * x));   // single MUFU
}
__device__ __forceinline__ uint32_t f2tf32(float x) {
    uint32_t r; asm("cvt.rna.tf32.f32 %0, %1;" : "=r"(r) : "f"(x)); return r;
}
__device__ __forceinline__ void mma_tf32(float c[4],
    uint32_t a0, uint32_t a1, uint32_t a2, uint32_t a3, uint32_t b0, uint32_t b1)
{
    asm volatile(
        "mma.sync.aligned.m16n8k8.row.col.f32.tf32.tf32.f32 "
        "{%0,%1,%2,%3}, {%4,%5,%6,%7}, {%8,%9}, {%0,%1,%2,%3};"
        : "+f"(c[0]), "+f"(c[1]), "+f"(c[2]), "+f"(c[3])
        : "r"(a0), "r"(a1), "r"(a2), "r"(a3), "r"(b0), "r"(b1));
}

// coalesced copy of one 8192-float frag set (hi+lo) into smem
__device__ __forceinline__ void copy_frag(const float* __restrict__ src,
                                          float* __restrict__ dst, int tid)
{
    const float4* s4 = (const float4*)src;
    float4* d4 = (float4*)dst;
    #pragma unroll
    for (int i = 0; i < 8; i++) d4[tid + 256 * i] = s4[tid + 256 * i];
}

// ---------------- R9 champion FFMA2 microkernel (pre only) ----------------
#define FFMA2_BLOCK(ha, hb, w)                                              \
    {                                                                       \
        ull_t p0 = pack2(ha.x, ha.x), p1 = pack2(ha.y, ha.y);               \
        ull_t p2 = pack2(ha.z, ha.z), p3 = pack2(ha.w, ha.w);               \
        ull_t p4 = pack2(hb.x, hb.x), p5 = pack2(hb.y, hb.y);               \
        ull_t p6 = pack2(hb.z, hb.z), p7 = pack2(hb.w, hb.w);               \
        acc[0][0] = ffma2(p0, w.x, acc[0][0]); acc[0][1] = ffma2(p0, w.y, acc[0][1]); \
        acc[1][0] = ffma2(p1, w.x, acc[1][0]); acc[1][1] = ffma2(p1, w.y, acc[1][1]); \
        acc[2][0] = ffma2(p2, w.x, acc[2][0]); acc[2][1] = ffma2(p2, w.y, acc[2][1]); \
        acc[3][0] = ffma2(p3, w.x, acc[3][0]); acc[3][1] = ffma2(p3, w.y, acc[3][1]); \
        acc[4][0] = ffma2(p4, w.x, acc[4][0]); acc[4][1] = ffma2(p4, w.y, acc[4][1]); \
        acc[5][0] = ffma2(p5, w.x, acc[5][0]); acc[5][1] = ffma2(p5, w.y, acc[5][1]); \
        acc[6][0] = ffma2(p6, w.x, acc[6][0]); acc[6][1] = ffma2(p6, w.y, acc[6][1]); \
        acc[7][0] = ffma2(p7, w.x, acc[7][0]); acc[7][1] = ffma2(p7, w.y, acc[7][1]); \
    }

template <int K, int ISTRIDE, int WSTRIDE, int HALF>
__device__ __forceinline__ void gemm_8x4(
    const float* __restrict__ inT, const float* __restrict__ W, ull_t acc[8][2])
{
    float4 ha = *(const float4*)(inT);
    float4 hb = *(const float4*)(inT + HALF);
    ulonglong2 w = *(const ulonglong2*)(W);
    #pragma unroll 8
    for (int k = 0; k < K; k++) {
        float4 nha, nhb; ulonglong2 nw;
        if (k + 1 < K) {
            nha = *(const float4*)(inT + (k + 1) * ISTRIDE);
            nhb = *(const float4*)(inT + (k + 1) * ISTRIDE + HALF);
            nw  = *(const ulonglong2*)(W + (k + 1) * WSTRIDE);
        }
        FFMA2_BLOCK(ha, hb, w);
        ha = nha; hb = nhb; w = nw;
    }
}

__device__ __forceinline__ void zero_acc(ull_t acc[8][2]) {
    #pragma unroll
    for (int i = 0; i < 8; i++) { acc[i][0] = 0ULL; acc[i][1] = 0ULL; }
}

// ============================================================
// Kernel 0: W-fragment precompute, one CTA per 64x64 set (9 CTAs)
//   frag (kt,nt) lane l: float2( W[8kt+tig][8nt+gid], W[8kt+tig+4][8nt+gid] )
// ============================================================
__device__ __forceinline__ void build_one(
    const float* __restrict__ src, float* __restrict__ dst, int tid)
{
    for (int idx = tid; idx < 2048; idx += 256) {
        int kt = idx >> 8;
        int nt = (idx >> 5) & 7;
        int ln = idx & 31;
        int g = ln >> 2, t = ln & 3;
        int r = 8 * kt + t, c = 8 * nt + g;
        float w0 = src[r * 64 + c];
        float w1 = src[(r + 4) * 64 + c];
        uint32_t h0 = f2tf32(w0), h1 = f2tf32(w1);
        dst[2 * idx]            = __uint_as_float(h0);
        dst[2 * idx + 1]        = __uint_as_float(h1);
        dst[4096 + 2 * idx]     = __uint_as_float(f2tf32(w0 - __uint_as_float(h0)));
        dst[4096 + 2 * idx + 1] = __uint_as_float(f2tf32(w1 - __uint_as_float(h1)));
    }
}

__global__ void wfrag_kernel(
    const float* __restrict__ msg_w2,  const float* __restrict__ mpos_w2,
    const float* __restrict__ upd_w1,  const float* __restrict__ upd_w2,
    const float* __restrict__ upe_w1,  const float* __restrict__ upe_w2)
{
    int tid = threadIdx.x;
    int b = blockIdx.x;
    switch (b) {
        case 0: build_one(msg_w2,  g_fragM, tid); break;
        case 1: build_one(mpos_w2, g_fragP, tid); break;
        case 2: case 3: case 4:
            build_one(upd_w1 + (b - 2) * 4096, g_fragUpd + (b - 2) * 8192, tid); break;
        case 5: build_one(upd_w2, g_fragUpd + 3 * 8192, tid); break;
        case 6: case 7:
            build_one(upe_w1 + (b - 6) * 4096, g_fragUpe + (b - 6) * 8192, tid); break;
        default: build_one(upe_w2, g_fragUpe + 2 * 8192, tid); break;
    }
}

// ============================================================
// Kernel 1 (fused): blockIdx.y==0 -> A,B (+zero aggr); ==1 -> P,Q
// (unchanged R11/R13 champion)
// ============================================================
__global__ void __launch_bounds__(256, 3) pre_kernel(
    const float* __restrict__ x, const float* __restrict__ pe,
    const float* __restrict__ msg_w1, const float* __restrict__ msg_b1,
    const float* __restrict__ mpos_w1, const float* __restrict__ mpos_b1,
    int N)
{
    extern __shared__ float sm[];
    float* sh_inT = sm;                   // [64][68]
    float* sh_W   = sh_inT + 64 * 68;     // [64][128]
    float* sh_b   = sh_W + 64 * 128;      // [128]

    int tid = threadIdx.x;
    int nb = blockIdx.x * 64;
    int tr = tid & 7, tc = tid >> 3;
    int r0 = 4 * tr, c0 = 4 * tc;

    ull_t acc[8][2];
    zero_acc(acc);
    float* dstA;
    float* dstB;

    if (blockIdx.y == 0) {
        if (tid < 128) sh_b[tid] = (tid < 64) ? msg_b1[tid] : 0.0f;
        for (int idx = tid; idx < 2048; idx += 256) {
            int n = idx & 63, s = (idx >> 6) & 15, which = idx >> 10;
            int gn = nb + n;
            if (gn < N) {
                float4* dst = (float4*)((which ? g_aggrp : g_aggr) + (size_t)gn * 64) + s;
                *dst = make_float4(0.f, 0.f, 0.f, 0.f);
            }
        }
        #pragma unroll 1
        for (int ch = 0; ch < 2; ch++) {
            __syncthreads();
            for (int idx = tid; idx < 64 * 128; idx += 256) {
                int k = idx >> 7, c = idx & 127;
                sh_W[idx] = (c < 64) ? msg_w1[(ch * 64 + k) * 64 + c]
                                     : msg_w1[(128 + ch * 64 + k) * 64 + (c - 64)];
            }
            const float* src = (ch == 0) ? x : pe;
            for (int idx = tid; idx < 16 * 64; idx += 256) {
                int n = idx & 63, k4 = idx >> 6;
                int gn = nb + n;
                float4 v = make_float4(0.f, 0.f, 0.f, 0.f);
                if (gn < N) v = *(const float4*)(src + (size_t)gn * 64 + 4 * k4);
                sh_inT[(4 * k4 + 0) * 68 + n] = v.x;
                sh_inT[(4 * k4 + 1) * 68 + n] = v.y;
                sh_inT[(4 * k4 + 2) * 68 + n] = v.z;
                sh_inT[(4 * k4 + 3) * 68 + n] = v.w;
            }
            __syncthreads();
            gemm_8x4<64, 68, 128, 32>(sh_inT + r0, sh_W + c0, acc);
        }
        dstA = g_A; dstB = g_B;
    } else {
        if (tid < 128) sh_b[tid] = (tid < 64) ? mpos_b1[tid] : 0.0f;
        for (int idx = tid; idx < 64 * 128; idx += 256) {
            int k = idx >> 7, c = idx & 127;
            sh_W[idx] = (c < 64) ? mpos_w1[k * 64 + c]
                                 : mpos_w1[(64 + k) * 64 + (c - 64)];
        }
        for (int idx = tid; idx < 16 * 64; idx += 256) {
            int n = idx & 63, k4 = idx >> 6;
            int gn = nb + n;
            float4 v = make_float4(0.f, 0.f, 0.f, 0.f);
            if (gn < N) v = *(const float4*)(pe + (size_t)gn * 64 + 4 * k4);
            sh_inT[(4 * k4 + 0) * 68 + n] = v.x;
            sh_inT[(4 * k4 + 1) * 68 + n] = v.y;
            sh_inT[(4 * k4 + 2) * 68 + n] = v.z;
            sh_inT[(4 * k4 + 3) * 68 + n] = v.w;
        }
        __syncthreads();
        gemm_8x4<64, 68, 128, 32>(sh_inT + r0, sh_W + c0, acc);
        dstA = g_P; dstB = g_Q;
    }

    float* dst = (c0 < 64) ? dstA : dstB;
    int lc = c0 & 63;
    float b0 = sh_b[c0], b1 = sh_b[c0 + 1], b2 = sh_b[c0 + 2], b3 = sh_b[c0 + 3];
    #pragma unroll
    for (int i = 0; i < 8; i++) {
        int rr = (i < 4) ? (r0 + i) : (32 + r0 + i - 4);
        int gn = nb + rr;
        if (gn < N) {
            float o0, o1, o2, o3;
            unpack2(acc[i][0], o0, o1);
            unpack2(acc[i][1], o2, o3);
            *(float4*)(dst + (size_t)gn * 64 + lc) =
                make_float4(o0 + b0, o1 + b1, o2 + b2, o3 + b3);
        }
    }
}

// ============================================================
// Kernel 2: edge kernel — tf32 mma, frags copied from global
// (unchanged R13 champion)
// ============================================================
template <bool IS_TANH>
__device__ __forceinline__ void edge_mma_path(
    const float* __restrict__ sh_t, const float* __restrict__ sh_Whi,
    const float* __restrict__ sh_Wlo, const float* __restrict__ bias,
    const int* __restrict__ rec, float* __restrict__ aggr,
    int w, int lane, int eb, int E)
{
    int gid = lane >> 2, tig = lane & 3;
    int e0 = w * 16;

    float acc[8][4];
    #pragma unroll
    for (int nt = 0; nt < 8; nt++) {
        acc[nt][0] = 0.f; acc[nt][1] = 0.f; acc[nt][2] = 0.f; acc[nt][3] = 0.f;
    }

    #pragma unroll 2
    for (int kt = 0; kt < 8; kt++) {
        const float* tk = sh_t + (8 * kt + tig) * 132 + e0 + gid;
        float a0f = tk[0],       a1f = tk[8];
        float a2f = tk[4 * 132], a3f = tk[4 * 132 + 8];
        uint32_t a0h = f2tf32(a0f), a1h = f2tf32(a1f);
        uint32_t a2h = f2tf32(a2f), a3h = f2tf32(a3f);
        uint32_t a0l = f2tf32(a0f - __uint_as_float(a0h));
        uint32_t a1l = f2tf32(a1f - __uint_as_float(a1h));
        uint32_t a2l = f2tf32(a2f - __uint_as_float(a2h));
        uint32_t a3l = f2tf32(a3f - __uint_as_float(a3h));
        #pragma unroll
        for (int nt = 0; nt < 8; nt++) {
            int fo = ((kt * 8 + nt) * 32 + lane) * 2;
            float2 bh = *(const float2*)(sh_Whi + fo);
            float2 bl = *(const float2*)(sh_Wlo + fo);
            uint32_t bh0 = __float_as_uint(bh.x), bh1 = __float_as_uint(bh.y);
            uint32_t bl0 = __float_as_uint(bl.x), bl1 = __float_as_uint(bl.y);
            mma_tf32(acc[nt], a0h, a1h, a2h, a3h, bh0, bh1);
            mma_tf32(acc[nt], a0h, a1h, a2h, a3h, bl0, bl1);
            mma_tf32(acc[nt], a0l, a1l, a2l, a3l, bh0, bh1);
        }
    }

    int el0 = e0 + gid, el1 = el0 + 8;
    bool v0 = (eb + el0 < E), v1 = (eb + el1 < E);
    int rc0 = rec[el0], rc1 = rec[el1];
    #pragma unroll
    for (int nt = 0; nt < 8; nt++) {
        int c = 8 * nt + 2 * tig;
        float b0 = bias[c], b1 = bias[c + 1];
        if (v0) {
            float m0 = acc[nt][0] + b0, m1 = acc[nt][1] + b1;
            if (IS_TANH) { m0 = tanh_f(m0); m1 = tanh_f(m1); }
            else         { m0 = silu_f(m0); m1 = silu_f(m1); }
            float* dst = aggr + (size_t)rc0 * 64 + c;
            asm volatile("red.global.add.v2.f32 [%0], {%1,%2};"
                         :: "l"(dst), "f"(m0), "f"(m1) : "memory");
        }
        if (v1) {
            float m0 = acc[nt][2] + b0, m1 = acc[nt][3] + b1;
            if (IS_TANH) { m0 = tanh_f(m0); m1 = tanh_f(m1); }
            else         { m0 = silu_f(m0); m1 = silu_f(m1); }
            float* dst = aggr + (size_t)rc1 * 64 + c;
            asm volatile("red.global.add.v2.f32 [%0], {%1,%2};"
                         :: "l"(dst), "f"(m0), "f"(m1) : "memory");
        }
    }
}

__global__ void __launch_bounds__(256, 3) edge_kernel(
    const float* __restrict__ pos,
    const int* __restrict__ ei,          // int32 (JAX demotes int64)
    const float* __restrict__ msg_w1,
    const float* __restrict__ msg_b2,
    const float* __restrict__ mpos_w1,
    const float* __restrict__ mpos_b2,
    int E)
{
    extern __shared__ float sm[];
    float* sh_t   = sm;                    // [64][132]
    float* sh_Whi = sh_t + 64 * 132;       // 4096 (hi; lo contiguous)
    float* sh_Wlo = sh_Whi + 4096;         // 4096
    float* sh_we  = sh_Wlo + 4096;         // [64]
    float* sh_ve  = sh_we + 64;
    float* sh_bm  = sh_ve + 64;
    float* sh_bp  = sh_bm + 64;
    int*   sh_rec = (int*)(sh_bp + 64);    // [128]

    int tid = threadIdx.x;
    copy_frag(g_fragM, sh_Whi, tid);
    if (tid < 64) {
        sh_we[tid] = msg_w1[256 * 64 + tid];
        sh_ve[tid] = mpos_w1[128 * 64 + tid];
        sh_bm[tid] = msg_b2[tid];
        sh_bp[tid] = mpos_b2[tid];
    }

    int eb = blockIdx.x * 128;
    int e  = tid & 127;
    int half = tid >> 7;
    int eg = eb + e;
    bool valid = eg < E;
    int snd = 0, rcv = 0;
    if (valid) { snd = ei[eg]; rcv = ei[E + eg]; }
    if (half == 0) sh_rec[e] = rcv;
    float dist = 0.0f;
    if (valid) {
        float dx = pos[snd * 3 + 0] - pos[rcv * 3 + 0];
        float dy = pos[snd * 3 + 1] - pos[rcv * 3 + 1];
        float dz = pos[snd * 3 + 2] - pos[rcv * 3 + 2];
        dist = sqrtf(dx * dx + dy * dy + dz * dz);
    }
    __syncthreads();

    int c0h = half * 32;
    int w = tid >> 5, lane = tid & 31;

    // ---- phase A: silu(A[snd]+B[rcv]+dist*we) -> sh_t, then msg GEMM ----
    {
        const float4* A4 = (const float4*)(g_A + (size_t)snd * 64 + c0h);
        const float4* B4 = (const float4*)(g_B + (size_t)rcv * 64 + c0h);
        const float4* W4 = (const float4*)(sh_we + c0h);
        #pragma unroll
        for (int j = 0; j < 8; j++) {
            float4 a = A4[j], b = B4[j], wv = W4[j];
            float* dst = sh_t + (c0h + 4 * j) * 132 + e;
            dst[0]   = silu_f(a.x + b.x + dist * wv.x);
            dst[132] = silu_f(a.y + b.y + dist * wv.y);
            dst[264] = silu_f(a.z + b.z + dist * wv.z);
            dst[396] = silu_f(a.w + b.w + dist * wv.w);
        }
    }
    __syncthreads();
    edge_mma_path<false>(sh_t, sh_Whi, sh_Wlo, sh_bm, sh_rec, g_aggr, w, lane, eb, E);
    __syncthreads();

    // ---- phase B: copy pos frags; tanh tile; pos GEMM ----
    copy_frag(g_fragP, sh_Whi, tid);
    {
        const float4* P4 = (const float4*)(g_P + (size_t)snd * 64 + c0h);
        const float4* Q4 = (const float4*)(g_Q + (size_t)rcv * 64 + c0h);
        const float4* V4 = (const float4*)(sh_ve + c0h);
        #pragma unroll
        for (int j = 0; j < 8; j++) {
            float4 p = P4[j], q = Q4[j], v = V4[j];
            float* dst = sh_t + (c0h + 4 * j) * 132 + e;
            dst[0]   = tanh_f(p.x + q.x + dist * v.x);
            dst[132] = tanh_f(p.y + q.y + dist * v.y);
            dst[264] = tanh_f(p.z + q.z + dist * v.z);
            dst[396] = tanh_f(p.w + q.w + dist * v.w);
        }
    }
    __syncthreads();
    edge_mma_path<true>(sh_t, sh_Whi, sh_Wlo, sh_bp, sh_rec, g_aggrp, w, lane, eb, E);
}

// ============================================================
// Kernel 3 (fused): tf32 mma with precomputed frags
//   blockIdx.y==0 -> update; ==1 -> update_pe.  128 nodes/CTA,
//   8 warps x (1 m-tile x 8 nt-tiles) — R12-validated mapping.
// ============================================================
__global__ void __launch_bounds__(256, 3) upd_kernel(
    const float* __restrict__ x, const float* __restrict__ pe,
    const float* __restrict__ upd_b1, const float* __restrict__ upd_b2,
    const float* __restrict__ upe_b1, const float* __restrict__ upe_b2,
    float* __restrict__ out, int N)
{
    extern __shared__ float sm[];
    float* sh_inT = sm;                    // [64][132] (chunk; reused as hT)
    float* sh_Whi = sh_inT + 64 * 132;     // 4096
    float* sh_Wlo = sh_Whi + 4096;         // 4096
    float* sh_b1  = sh_Wlo + 4096;         // [64]
    float* sh_b2  = sh_b1 + 64;            // [64]

    bool is_pe = (blockIdx.y != 0);
    const float* fragbase = is_pe ? g_fragUpe : g_fragUpd;
    int nchunks = is_pe ? 2 : 3;

    int tid = threadIdx.x;
    int nb = blockIdx.x * 128;
    if (tid < 64) {
        sh_b1[tid] = is_pe ? upe_b1[tid] : upd_b1[tid];
        sh_b2[tid] = is_pe ? upe_b2[tid] : upd_b2[tid];
    }

    int w = tid >> 5, lane = tid & 31;
    int gid = lane >> 2, tig = lane & 3;
    int m0 = w * 16;                       // node rows [m0, m0+16)

    float acc[8][4];
    #pragma unroll
    for (int nt = 0; nt < 8; nt++) {
        acc[nt][0] = 0.f; acc[nt][1] = 0.f; acc[nt][2] = 0.f; acc[nt][3] = 0.f;
    }

    // -------- GEMM 1: h = in @ W1, K chunked by 64 --------
    #pragma unroll 1
    for (int ch = 0; ch < nchunks; ch++) {
        __syncthreads();   // previous chunk's frag/inT reads complete
        copy_frag(fragbase + ch * 8192, sh_Whi, tid);
        const float* src = is_pe ? ((ch == 0) ? pe : g_aggrp)
                                 : ((ch == 0) ? x : (ch == 1) ? pe : g_aggr);
        for (int idx = tid; idx < 16 * 128; idx += 256) {
            int n = idx & 127, k4 = idx >> 7;
            int gn = nb + n;
            float4 v = make_float4(0.f, 0.f, 0.f, 0.f);
            if (gn < N) v = *(const float4*)(src + (size_t)gn * 64 + 4 * k4);
            sh_inT[(4 * k4 + 0) * 132 + n] = v.x;
            sh_inT[(4 * k4 + 1) * 132 + n] = v.y;
            sh_inT[(4 * k4 + 2) * 132 + n] = v.z;
            sh_inT[(4 * k4 + 3) * 132 + n] = v.w;
        }
        __syncthreads();
        #pragma unroll 2
        for (int kt = 0; kt < 8; kt++) {
            const float* tk = sh_inT + (8 * kt + tig) * 132 + m0 + gid;
            float a0f = tk[0],       a1f = tk[8];
            float a2f = tk[4 * 132], a3f = tk[4 * 132 + 8];
            uint32_t ah0 = f2tf32(a0f), ah1 = f2tf32(a1f);
            uint32_t ah2 = f2tf32(a2f), ah3 = f2tf32(a3f);
            uint32_t al0 = f2tf32(a0f - __uint_as_float(ah0));
            uint32_t al1 = f2tf32(a1f - __uint_as_float(ah1));
            uint32_t al2 = f2tf32(a2f - __uint_as_float(ah2));
            uint32_t al3 = f2tf32(a3f - __uint_as_float(ah3));
            #pragma unroll
            for (int nt = 0; nt < 8; nt++) {
                int fo = ((kt * 8 + nt) * 32 + lane) * 2;
                float2 bh = *(const float2*)(sh_Whi + fo);
                float2 bl = *(const float2*)(sh_Wlo + fo);
                uint32_t bh0 = __float_as_uint(bh.x), bh1 = __float_as_uint(bh.y);
                uint32_t bl0 = __float_as_uint(bl.x), bl1 = __float_as_uint(bl.y);
                mma_tf32(acc[nt], ah0, ah1, ah2, ah3, bh0, bh1);
                mma_tf32(acc[nt], ah0, ah1, ah2, ah3, bl0, bl1);
                mma_tf32(acc[nt], al0, al1, al2, al3, bh0, bh1);
            }
        }
    }

    // -------- activation -> hT (over inT); copy W2 frags --------
    __syncthreads();   // all GEMM-1 reads of inT/frags complete
    #pragma unroll
    for (int nt = 0; nt < 8; nt++) {
        int c = 8 * nt + 2 * tig;
        float b0 = sh_b1[c], b1 = sh_b1[c + 1];
        float h00 = acc[nt][0] + b0, h01 = acc[nt][1] + b1;   // row m0+gid
        float h10 = acc[nt][2] + b0, h11 = acc[nt][3] + b1;   // row m0+gid+8
        if (is_pe) { h00 = tanh_f(h00); h01 = tanh_f(h01); h10 = tanh_f(h10); h11 = tanh_f(h11); }
        else       { h00 = silu_f(h00); h01 = silu_f(h01); h10 = silu_f(h10); h11 = silu_f(h11); }
        sh_inT[c * 132 + m0 + gid]           = h00;
        sh_inT[(c + 1) * 132 + m0 + gid]     = h01;
        sh_inT[c * 132 + m0 + gid + 8]       = h10;
        sh_inT[(c + 1) * 132 + m0 + gid + 8] = h11;
    }
    copy_frag(fragbase + (is_pe ? 2 : 3) * 8192, sh_Whi, tid);
    __syncthreads();

    // -------- GEMM 2: out = h @ W2 --------
    float a2[8][4];
    #pragma unroll
    for (int nt = 0; nt < 8; nt++) {
        a2[nt][0] = 0.f; a2[nt][1] = 0.f; a2[nt][2] = 0.f; a2[nt][3] = 0.f;
    }
    #pragma unroll 2
    for (int kt = 0; kt < 8; kt++) {
        const float* tk = sh_inT + (8 * kt + tig) * 132 + m0 + gid;
        float a0f = tk[0],       a1f = tk[8];
        float a2f = tk[4 * 132], a3f = tk[4 * 132 + 8];
        uint32_t ah0 = f2tf32(a0f), ah1 = f2tf32(a1f);
        uint32_t ah2 = f2tf32(a2f), ah3 = f2tf32(a3f);
        uint32_t al0 = f2tf32(a0f - __uint_as_float(ah0));
        uint32_t al1 = f2tf32(a1f - __uint_as_float(ah1));
        uint32_t al2 = f2tf32(a2f - __uint_as_float(ah2));
        uint32_t al3 = f2tf32(a3f - __uint_as_float(ah3));
        #pragma unroll
        for (int nt = 0; nt < 8; nt++) {
            int fo = ((kt * 8 + nt) * 32 + lane) * 2;
            float2 bh = *(const float2*)(sh_Whi + fo);
            float2 bl = *(const float2*)(sh_Wlo + fo);
            uint32_t bh0 = __float_as_uint(bh.x), bh1 = __float_as_uint(bh.y);
            uint32_t bl0 = __float_as_uint(bl.x), bl1 = __float_as_uint(bl.y);
            mma_tf32(a2[nt], ah0, ah1, ah2, ah3, bh0, bh1);
            mma_tf32(a2[nt], ah0, ah1, ah2, ah3, bl0, bl1);
            mma_tf32(a2[nt], al0, al1, al2, al3, bh0, bh1);
        }
    }

    float* obase = out + (is_pe ? (size_t)N * 64 : 0);
    int g0 = nb + m0 + gid, g1 = g0 + 8;
    #pragma unroll
    for (int nt = 0; nt < 8; nt++) {
        int c = 8 * nt + 2 * tig;
        float b0 = sh_b2[c], b1 = sh_b2[c + 1];
        if (g0 < N) {
            float o0 = a2[nt][0] + b0, o1 = a2[nt][1] + b1;
            if (is_pe) { o0 = tanh_f(o0); o1 = tanh_f(o1); }
            *(float2*)(obase + (size_t)g0 * 64 + c) = make_float2(o0, o1);
        }
        if (g1 < N) {
            float o0 = a2[nt][2] + b0, o1 = a2[nt][3] + b1;
            if (is_pe) { o0 = tanh_f(o0); o1 = tanh_f(o1); }
            *(float2*)(obase + (size_t)g1 * 64 + c) = make_float2(o0, o1);
        }
    }
}

// ============================================================
// Host launch
// ============================================================
extern "C" void kernel_launch(void* const* d_in, const int* in_sizes, int n_in,
                              void* d_out, int out_size)
{
    const float* x       = (const float*)d_in[0];
    const float* pos     = (const float*)d_in[1];
    const float* pe      = (const float*)d_in[2];
    const int*   ei      = (const int*)d_in[3];
    const float* msg_w1  = (const float*)d_in[4];
    const float* msg_b1  = (const float*)d_in[5];
    const float* msg_w2  = (const float*)d_in[6];
    const float* msg_b2  = (const float*)d_in[7];
    const float* mpos_w1 = (const float*)d_in[8];
    const float* mpos_b1 = (const float*)d_in[9];
    const float* mpos_w2 = (const float*)d_in[10];
    const float* mpos_b2 = (const float*)d_in[11];
    const float* upd_w1  = (const float*)d_in[12];
    const float* upd_b1  = (const float*)d_in[13];
    const float* upd_w2  = (const float*)d_in[14];
    const float* upd_b2  = (const float*)d_in[15];
    const float* upe_w1  = (const float*)d_in[16];
    const float* upe_b1  = (const float*)d_in[17];
    const float* upe_w2  = (const float*)d_in[18];
    const float* upe_b2  = (const float*)d_in[19];

    int N = in_sizes[0] / 64;
    int E = in_sizes[3] / 2;

    const int SMEM_PRE  = (64 * 68 + 64 * 128 + 128) * 4;                  // 50,688 B
    const int SMEM_EDGE = (64 * 132 + 4096 + 4096 + 256) * 4 + 512;        // 68,096 B
    const int SMEM_UPD  = (64 * 132 + 4096 + 4096 + 128) * 4;              // 67,072 B

    cudaFuncSetAttribute(pre_kernel,  cudaFuncAttributeMaxDynamicSharedMemorySize, SMEM_PRE);
    cudaFuncSetAttribute(edge_kernel, cudaFuncAttributeMaxDynamicSharedMemorySize, SMEM_EDGE);
    cudaFuncSetAttribute(upd_kernel,  cudaFuncAttributeMaxDynamicSharedMemorySize, SMEM_UPD);

    dim3 gpre((N + 63) / 64, 2);
    dim3 gupd((N + 127) / 128, 2);
    wfrag_kernel<<<9, 256>>>(msg_w2, mpos_w2, upd_w1, upd_w2, upe_w1, upe_w2);
    pre_kernel<<<gpre, 256, SMEM_PRE>>>(x, pe, msg_w1, msg_b1, mpos_w1, mpos_b1, N);
    edge_kernel<<<(E + 127) / 128, 256, SMEM_EDGE>>>(pos, ei, msg_w1, msg_b2,
                                                     mpos_w1, mpos_b2, E);
    upd_kernel<<<gupd, 256, SMEM_UPD>>>(x, pe, upd_b1, upd_b2, upe_b1, upe_b2,
                                        (float*)d_out, N);
}

// round 15
// speedup vs baseline: 1.1398x; 1.0121x over previous
#include <cuda_runtime.h>
#include <cstdint>

#define NV_MAX 50000
#define HDIM 64

// -------- scratch (no allocs allowed) --------
__device__ float g_A[NV_MAX * HDIM];
__device__ float g_B[NV_MAX * HDIM];
__device__ float g_P[NV_MAX * HDIM];
__device__ float g_Q[NV_MAX * HDIM];
__device__ float g_aggr[NV_MAX * HDIM];
__device__ float g_aggrp[NV_MAX * HDIM];
// precomputed tf32 W fragments (hi[4096] ++ lo[4096] per 64x64 set)
__device__ float g_fragM[8192];            // msg_w2
__device__ float g_fragP[8192];            // mpos_w2
__device__ float g_fragUpd[4 * 8192];      // upd_w1 ch0..2, upd_w2
__device__ float g_fragUpe[3 * 8192];      // upe_w1 ch0..1, upe_w2
__device__ float g_fragPreM[4 * 8192];     // msg_w1 blocks (nh,kc)=(0,0),(0,1),(1,0),(1,1)
__device__ float g_fragPreP[2 * 8192];     // mpos_w1 blocks nh=0,1

typedef unsigned long long ull_t;

__device__ __forceinline__ float tanh_f(float x) {
    float y; asm("tanh.approx.f32 %0, %1;" : "=f"(y) : "f"(x)); return y;
}
__device__ __forceinline__ float silu_f(float x) {
    return 0.5f * x * (1.0f + tanh_f(0.5f * x));   // single MUFU
}
__device__ __forceinline__ uint32_t f2tf32(float x) {
    uint32_t r; asm("cvt.rna.tf32.f32 %0, %1;" : "=r"(r) : "f"(x)); return r;
}
__device__ __forceinline__ void mma_tf32(float c[4],
    uint32_t a0, uint32_t a1, uint32_t a2, uint32_t a3, uint32_t b0, uint32_t b1)
{
    asm volatile(
        "mma.sync.aligned.m16n8k8.row.col.f32.tf32.tf32.f32 "
        "{%0,%1,%2,%3}, {%4,%5,%6,%7}, {%8,%9}, {%0,%1,%2,%3};"
        : "+f"(c[0]), "+f"(c[1]), "+f"(c[2]), "+f"(c[3])
        : "r"(a0), "r"(a1), "r"(a2), "r"(a3), "r"(b0), "r"(b1));
}

// coalesced copy of one 8192-float frag set (hi+lo) into smem
__device__ __forceinline__ void copy_frag(const float* __restrict__ src,
                                          float* __restrict__ dst, int tid)
{
    const float4* s4 = (const float4*)src;
    float4* d4 = (float4*)dst;
    #pragma unroll
    for (int i = 0; i < 8; i++) d4[tid + 256 * i] = s4[tid + 256 * i];
}

// ============================================================
// Kernel 0: W-fragment precompute, one CTA per 64x64 set (15 CTAs)
//   frag (kt,nt) lane l: float2( W[8kt+tig][8nt+gid], W[8kt+tig+4][8nt+gid] )
// ============================================================
__device__ __forceinline__ void build_one(
    const float* __restrict__ src, float* __restrict__ dst, int tid)
{
    for (int idx = tid; idx < 2048; idx += 256) {
        int kt = idx >> 8;
        int nt = (idx >> 5) & 7;
        int ln = idx & 31;
        int g = ln >> 2, t = ln & 3;
        int r = 8 * kt + t, c = 8 * nt + g;
        float w0 = src[r * 64 + c];
        float w1 = src[(r + 4) * 64 + c];
        uint32_t h0 = f2tf32(w0), h1 = f2tf32(w1);
        dst[2 * idx]            = __uint_as_float(h0);
        dst[2 * idx + 1]        = __uint_as_float(h1);
        dst[4096 + 2 * idx]     = __uint_as_float(f2tf32(w0 - __uint_as_float(h0)));
        dst[4096 + 2 * idx + 1] = __uint_as_float(f2tf32(w1 - __uint_as_float(h1)));
    }
}

__global__ void wfrag_kernel(
    const float* __restrict__ msg_w1,  const float* __restrict__ msg_w2,
    const float* __restrict__ mpos_w1, const float* __restrict__ mpos_w2,
    const float* __restrict__ upd_w1,  const float* __restrict__ upd_w2,
    const float* __restrict__ upe_w1,  const float* __restrict__ upe_w2)
{
    int tid = threadIdx.x;
    int b = blockIdx.x;
    if (b == 0)       build_one(msg_w2,  g_fragM, tid);
    else if (b == 1)  build_one(mpos_w2, g_fragP, tid);
    else if (b <= 4)  build_one(upd_w1 + (b - 2) * 4096, g_fragUpd + (b - 2) * 8192, tid);
    else if (b == 5)  build_one(upd_w2, g_fragUpd + 3 * 8192, tid);
    else if (b <= 7)  build_one(upe_w1 + (b - 6) * 4096, g_fragUpe + (b - 6) * 8192, tid);
    else if (b == 8)  build_one(upe_w2, g_fragUpe + 2 * 8192, tid);
    else if (b <= 12) {
        int s = b - 9;                 // s = nh*2 + kc
        int nh = s >> 1, kc = s & 1;
        build_one(msg_w1 + (nh * 128 + kc * 64) * 64, g_fragPreM + s * 8192, tid);
    } else {
        int nh = b - 13;
        build_one(mpos_w1 + nh * 64 * 64, g_fragPreP + nh * 8192, tid);
    }
}

// ============================================================
// Kernel 1 (fused, tf32 mma): blockIdx.y==0 -> A,B (+zero aggr); ==1 -> P,Q
//   128 nodes/CTA; 8 warps x (1 m-tile x 8 nt); outer loop over n-half.
// ============================================================
__global__ void __launch_bounds__(256, 3) pre_kernel(
    const float* __restrict__ x, const float* __restrict__ pe,
    const float* __restrict__ msg_b1, const float* __restrict__ mpos_b1,
    int N)
{
    extern __shared__ float sm[];
    float* sh_inT = sm;                    // [64][132]
    float* sh_Whi = sh_inT + 64 * 132;     // 4096
    float* sh_Wlo = sh_Whi + 4096;         // 4096
    float* sh_b   = sh_Wlo + 4096;         // [128]  (b1 | zeros)

    bool is_pos = (blockIdx.y != 0);
    const float* fragbase = is_pos ? g_fragPreP : g_fragPreM;
    int nkc = is_pos ? 1 : 2;

    int tid = threadIdx.x;
    int nb = blockIdx.x * 128;
    if (tid < 128) sh_b[tid] = (tid < 64) ? (is_pos ? mpos_b1[tid] : msg_b1[tid]) : 0.0f;

    if (!is_pos) {   // zero aggregation buffers (edge kernel runs after)
        for (int idx = tid; idx < 4096; idx += 256) {
            int n = idx & 127, s = (idx >> 7) & 15, which = idx >> 11;
            int gn = nb + n;
            if (gn < N) {
                float4* dst = (float4*)((which ? g_aggrp : g_aggr) + (size_t)gn * 64) + s;
                *dst = make_float4(0.f, 0.f, 0.f, 0.f);
            }
        }
    }

    int w = tid >> 5, lane = tid & 31;
    int gid = lane >> 2, tig = lane & 3;
    int m0 = w * 16;                       // node rows [m0, m0+16)

    #pragma unroll 1
    for (int nh = 0; nh < 2; nh++) {
        float acc[8][4];
        #pragma unroll
        for (int nt = 0; nt < 8; nt++) {
            acc[nt][0] = 0.f; acc[nt][1] = 0.f; acc[nt][2] = 0.f; acc[nt][3] = 0.f;
        }

        #pragma unroll 1
        for (int kc = 0; kc < nkc; kc++) {
            __syncthreads();   // prior GEMM/frag readers done
            copy_frag(fragbase + (nh * nkc + kc) * 8192, sh_Whi, tid);
            const float* src = is_pos ? pe : ((kc == 0) ? x : pe);
            for (int idx = tid; idx < 16 * 128; idx += 256) {
                int n = idx & 127, k4 = idx >> 7;
                int gn = nb + n;
                float4 v = make_float4(0.f, 0.f, 0.f, 0.f);
                if (gn < N) v = *(const float4*)(src + (size_t)gn * 64 + 4 * k4);
                sh_inT[(4 * k4 + 0) * 132 + n] = v.x;
                sh_inT[(4 * k4 + 1) * 132 + n] = v.y;
                sh_inT[(4 * k4 + 2) * 132 + n] = v.z;
                sh_inT[(4 * k4 + 3) * 132 + n] = v.w;
            }
            __syncthreads();
            #pragma unroll 2
            for (int kt = 0; kt < 8; kt++) {
                const float* tk = sh_inT + (8 * kt + tig) * 132 + m0 + gid;
                float a0f = tk[0],       a1f = tk[8];
                float a2f = tk[4 * 132], a3f = tk[4 * 132 + 8];
                uint32_t ah0 = f2tf32(a0f), ah1 = f2tf32(a1f);
                uint32_t ah2 = f2tf32(a2f), ah3 = f2tf32(a3f);
                uint32_t al0 = f2tf32(a0f - __uint_as_float(ah0));
                uint32_t al1 = f2tf32(a1f - __uint_as_float(ah1));
                uint32_t al2 = f2tf32(a2f - __uint_as_float(ah2));
                uint32_t al3 = f2tf32(a3f - __uint_as_float(ah3));
                #pragma unroll
                for (int nt = 0; nt < 8; nt++) {
                    int fo = ((kt * 8 + nt) * 32 + lane) * 2;
                    float2 bh = *(const float2*)(sh_Whi + fo);
                    float2 bl = *(const float2*)(sh_Wlo + fo);
                    uint32_t bh0 = __float_as_uint(bh.x), bh1 = __float_as_uint(bh.y);
                    uint32_t bl0 = __float_as_uint(bl.x), bl1 = __float_as_uint(bl.y);
                    mma_tf32(acc[nt], ah0, ah1, ah2, ah3, bh0, bh1);
                    mma_tf32(acc[nt], ah0, ah1, ah2, ah3, bl0, bl1);
                    mma_tf32(acc[nt], al0, al1, al2, al3, bh0, bh1);
                }
            }
        }

        float* dst = is_pos ? (nh ? g_Q : g_P) : (nh ? g_B : g_A);
        const float* bb = sh_b + nh * 64;
        int g0 = nb + m0 + gid, g1 = g0 + 8;
        #pragma unroll
        for (int nt = 0; nt < 8; nt++) {
            int c = 8 * nt + 2 * tig;
            float b0 = bb[c], b1 = bb[c + 1];
            if (g0 < N)
                *(float2*)(dst + (size_t)g0 * 64 + c) =
                    make_float2(acc[nt][0] + b0, acc[nt][1] + b1);
            if (g1 < N)
                *(float2*)(dst + (size_t)g1 * 64 + c) =
                    make_float2(acc[nt][2] + b0, acc[nt][3] + b1);
        }
    }
}

// ============================================================
// Kernel 2: edge kernel — tf32 mma, frags copied from global
// (unchanged R13/R14 champion)
// ============================================================
template <bool IS_TANH>
__device__ __forceinline__ void edge_mma_path(
    const float* __restrict__ sh_t, const float* __restrict__ sh_Whi,
    const float* __restrict__ sh_Wlo, const float* __restrict__ bias,
    const int* __restrict__ rec, float* __restrict__ aggr,
    int w, int lane, int eb, int E)
{
    int gid = lane >> 2, tig = lane & 3;
    int e0 = w * 16;

    float acc[8][4];
    #pragma unroll
    for (int nt = 0; nt < 8; nt++) {
        acc[nt][0] = 0.f; acc[nt][1] = 0.f; acc[nt][2] = 0.f; acc[nt][3] = 0.f;
    }

    #pragma unroll 2
    for (int kt = 0; kt < 8; kt++) {
        const float* tk = sh_t + (8 * kt + tig) * 132 + e0 + gid;
        float a0f = tk[0],       a1f = tk[8];
        float a2f = tk[4 * 132], a3f = tk[4 * 132 + 8];
        uint32_t a0h = f2tf32(a0f), a1h = f2tf32(a1f);
        uint32_t a2h = f2tf32(a2f), a3h = f2tf32(a3f);
        uint32_t a0l = f2tf32(a0f - __uint_as_float(a0h));
        uint32_t a1l = f2tf32(a1f - __uint_as_float(a1h));
        uint32_t a2l = f2tf32(a2f - __uint_as_float(a2h));
        uint32_t a3l = f2tf32(a3f - __uint_as_float(a3h));
        #pragma unroll
        for (int nt = 0; nt < 8; nt++) {
            int fo = ((kt * 8 + nt) * 32 + lane) * 2;
            float2 bh = *(const float2*)(sh_Whi + fo);
            float2 bl = *(const float2*)(sh_Wlo + fo);
            uint32_t bh0 = __float_as_uint(bh.x), bh1 = __float_as_uint(bh.y);
            uint32_t bl0 = __float_as_uint(bl.x), bl1 = __float_as_uint(bl.y);
            mma_tf32(acc[nt], a0h, a1h, a2h, a3h, bh0, bh1);
            mma_tf32(acc[nt], a0h, a1h, a2h, a3h, bl0, bl1);
            mma_tf32(acc[nt], a0l, a1l, a2l, a3l, bh0, bh1);
        }
    }

    int el0 = e0 + gid, el1 = el0 + 8;
    bool v0 = (eb + el0 < E), v1 = (eb + el1 < E);
    int rc0 = rec[el0], rc1 = rec[el1];
    #pragma unroll
    for (int nt = 0; nt < 8; nt++) {
        int c = 8 * nt + 2 * tig;
        float b0 = bias[c], b1 = bias[c + 1];
        if (v0) {
            float m0 = acc[nt][0] + b0, m1 = acc[nt][1] + b1;
            if (IS_TANH) { m0 = tanh_f(m0); m1 = tanh_f(m1); }
            else         { m0 = silu_f(m0); m1 = silu_f(m1); }
            float* dst = aggr + (size_t)rc0 * 64 + c;
            asm volatile("red.global.add.v2.f32 [%0], {%1,%2};"
                         :: "l"(dst), "f"(m0), "f"(m1) : "memory");
        }
        if (v1) {
            float m0 = acc[nt][2] + b0, m1 = acc[nt][3] + b1;
            if (IS_TANH) { m0 = tanh_f(m0); m1 = tanh_f(m1); }
            else         { m0 = silu_f(m0); m1 = silu_f(m1); }
            float* dst = aggr + (size_t)rc1 * 64 + c;
            asm volatile("red.global.add.v2.f32 [%0], {%1,%2};"
                         :: "l"(dst), "f"(m0), "f"(m1) : "memory");
        }
    }
}

__global__ void __launch_bounds__(256, 3) edge_kernel(
    const float* __restrict__ pos,
    const int* __restrict__ ei,          // int32 (JAX demotes int64)
    const float* __restrict__ msg_w1,
    const float* __restrict__ msg_b2,
    const float* __restrict__ mpos_w1,
    const float* __restrict__ mpos_b2,
    int E)
{
    extern __shared__ float sm[];
    float* sh_t   = sm;                    // [64][132]
    float* sh_Whi = sh_t + 64 * 132;       // 4096 (hi; lo contiguous)
    float* sh_Wlo = sh_Whi + 4096;         // 4096
    float* sh_we  = sh_Wlo + 4096;         // [64]
    float* sh_ve  = sh_we + 64;
    float* sh_bm  = sh_ve + 64;
    float* sh_bp  = sh_bm + 64;
    int*   sh_rec = (int*)(sh_bp + 64);    // [128]

    int tid = threadIdx.x;
    copy_frag(g_fragM, sh_Whi, tid);
    if (tid < 64) {
        sh_we[tid] = msg_w1[256 * 64 + tid];
        sh_ve[tid] = mpos_w1[128 * 64 + tid];
        sh_bm[tid] = msg_b2[tid];
        sh_bp[tid] = mpos_b2[tid];
    }

    int eb = blockIdx.x * 128;
    int e  = tid & 127;
    int half = tid >> 7;
    int eg = eb + e;
    bool valid = eg < E;
    int snd = 0, rcv = 0;
    if (valid) { snd = ei[eg]; rcv = ei[E + eg]; }
    if (half == 0) sh_rec[e] = rcv;
    float dist = 0.0f;
    if (valid) {
        float dx = pos[snd * 3 + 0] - pos[rcv * 3 + 0];
        float dy = pos[snd * 3 + 1] - pos[rcv * 3 + 1];
        float dz = pos[snd * 3 + 2] - pos[rcv * 3 + 2];
        dist = sqrtf(dx * dx + dy * dy + dz * dz);
    }
    __syncthreads();

    int c0h = half * 32;
    int w = tid >> 5, lane = tid & 31;

    // ---- phase A: silu(A[snd]+B[rcv]+dist*we) -> sh_t, then msg GEMM ----
    {
        const float4* A4 = (const float4*)(g_A + (size_t)snd * 64 + c0h);
        const float4* B4 = (const float4*)(g_B + (size_t)rcv * 64 + c0h);
        const float4* W4 = (const float4*)(sh_we + c0h);
        #pragma unroll
        for (int j = 0; j < 8; j++) {
            float4 a = A4[j], b = B4[j], wv = W4[j];
            float* dst = sh_t + (c0h + 4 * j) * 132 + e;
            dst[0]   = silu_f(a.x + b.x + dist * wv.x);
            dst[132] = silu_f(a.y + b.y + dist * wv.y);
            dst[264] = silu_f(a.z + b.z + dist * wv.z);
            dst[396] = silu_f(a.w + b.w + dist * wv.w);
        }
    }
    __syncthreads();
    edge_mma_path<false>(sh_t, sh_Whi, sh_Wlo, sh_bm, sh_rec, g_aggr, w, lane, eb, E);
    __syncthreads();

    // ---- phase B: copy pos frags; tanh tile; pos GEMM ----
    copy_frag(g_fragP, sh_Whi, tid);
    {
        const float4* P4 = (const float4*)(g_P + (size_t)snd * 64 + c0h);
        const float4* Q4 = (const float4*)(g_Q + (size_t)rcv * 64 + c0h);
        const float4* V4 = (const float4*)(sh_ve + c0h);
        #pragma unroll
        for (int j = 0; j < 8; j++) {
            float4 p = P4[j], q = Q4[j], v = V4[j];
            float* dst = sh_t + (c0h + 4 * j) * 132 + e;
            dst[0]   = tanh_f(p.x + q.x + dist * v.x);
            dst[132] = tanh_f(p.y + q.y + dist * v.y);
            dst[264] = tanh_f(p.z + q.z + dist * v.z);
            dst[396] = tanh_f(p.w + q.w + dist * v.w);
        }
    }
    __syncthreads();
    edge_mma_path<true>(sh_t, sh_Whi, sh_Wlo, sh_bp, sh_rec, g_aggrp, w, lane, eb, E);
}

// ============================================================
// Kernel 3 (fused): tf32 mma with precomputed frags
// (unchanged R14 champion)
// ============================================================
__global__ void __launch_bounds__(256, 3) upd_kernel(
    const float* __restrict__ x, const float* __restrict__ pe,
    const float* __restrict__ upd_b1, const float* __restrict__ upd_b2,
    const float* __restrict__ upe_b1, const float* __restrict__ upe_b2,
    float* __restrict__ out, int N)
{
    extern __shared__ float sm[];
    float* sh_inT = sm;                    // [64][132] (chunk; reused as hT)
    float* sh_Whi = sh_inT + 64 * 132;     // 4096
    float* sh_Wlo = sh_Whi + 4096;         // 4096
    float* sh_b1  = sh_Wlo + 4096;         // [64]
    float* sh_b2  = sh_b1 + 64;            // [64]

    bool is_pe = (blockIdx.y != 0);
    const float* fragbase = is_pe ? g_fragUpe : g_fragUpd;
    int nchunks = is_pe ? 2 : 3;

    int tid = threadIdx.x;
    int nb = blockIdx.x * 128;
    if (tid < 64) {
        sh_b1[tid] = is_pe ? upe_b1[tid] : upd_b1[tid];
        sh_b2[tid] = is_pe ? upe_b2[tid] : upd_b2[tid];
    }

    int w = tid >> 5, lane = tid & 31;
    int gid = lane >> 2, tig = lane & 3;
    int m0 = w * 16;

    float acc[8][4];
    #pragma unroll
    for (int nt = 0; nt < 8; nt++) {
        acc[nt][0] = 0.f; acc[nt][1] = 0.f; acc[nt][2] = 0.f; acc[nt][3] = 0.f;
    }

    #pragma unroll 1
    for (int ch = 0; ch < nchunks; ch++) {
        __syncthreads();
        copy_frag(fragbase + ch * 8192, sh_Whi, tid);
        const float* src = is_pe ? ((ch == 0) ? pe : g_aggrp)
                                 : ((ch == 0) ? x : (ch == 1) ? pe : g_aggr);
        for (int idx = tid; idx < 16 * 128; idx += 256) {
            int n = idx & 127, k4 = idx >> 7;
            int gn = nb + n;
            float4 v = make_float4(0.f, 0.f, 0.f, 0.f);
            if (gn < N) v = *(const float4*)(src + (size_t)gn * 64 + 4 * k4);
            sh_inT[(4 * k4 + 0) * 132 + n] = v.x;
            sh_inT[(4 * k4 + 1) * 132 + n] = v.y;
            sh_inT[(4 * k4 + 2) * 132 + n] = v.z;
            sh_inT[(4 * k4 + 3) * 132 + n] = v.w;
        }
        __syncthreads();
        #pragma unroll 2
        for (int kt = 0; kt < 8; kt++) {
            const float* tk = sh_inT + (8 * kt + tig) * 132 + m0 + gid;
            float a0f = tk[0],       a1f = tk[8];
            float a2f = tk[4 * 132], a3f = tk[4 * 132 + 8];
            uint32_t ah0 = f2tf32(a0f), ah1 = f2tf32(a1f);
            uint32_t ah2 = f2tf32(a2f), ah3 = f2tf32(a3f);
            uint32_t al0 = f2tf32(a0f - __uint_as_float(ah0));
            uint32_t al1 = f2tf32(a1f - __uint_as_float(ah1));
            uint32_t al2 = f2tf32(a2f - __uint_as_float(ah2));
            uint32_t al3 = f2tf32(a3f - __uint_as_float(ah3));
            #pragma unroll
            for (int nt = 0; nt < 8; nt++) {
                int fo = ((kt * 8 + nt) * 32 + lane) * 2;
                float2 bh = *(const float2*)(sh_Whi + fo);
                float2 bl = *(const float2*)(sh_Wlo + fo);
                uint32_t bh0 = __float_as_uint(bh.x), bh1 = __float_as_uint(bh.y);
                uint32_t bl0 = __float_as_uint(bl.x), bl1 = __float_as_uint(bl.y);
                mma_tf32(acc[nt], ah0, ah1, ah2, ah3, bh0, bh1);
                mma_tf32(acc[nt], ah0, ah1, ah2, ah3, bl0, bl1);
                mma_tf32(acc[nt], al0, al1, al2, al3, bh0, bh1);
            }
        }
    }

    __syncthreads();
    #pragma unroll
    for (int nt = 0; nt < 8; nt++) {
        int c = 8 * nt + 2 * tig;
        float b0 = sh_b1[c], b1 = sh_b1[c + 1];
        float h00 = acc[nt][0] + b0, h01 = acc[nt][1] + b1;
        float h10 = acc[nt][2] + b0, h11 = acc[nt][3] + b1;
        if (is_pe) { h00 = tanh_f(h00); h01 = tanh_f(h01); h10 = tanh_f(h10); h11 = tanh_f(h11); }
        else       { h00 = silu_f(h00); h01 = silu_f(h01); h10 = silu_f(h10); h11 = silu_f(h11); }
        sh_inT[c * 132 + m0 + gid]           = h00;
        sh_inT[(c + 1) * 132 + m0 + gid]     = h01;
        sh_inT[c * 132 + m0 + gid + 8]       = h10;
        sh_inT[(c + 1) * 132 + m0 + gid + 8] = h11;
    }
    copy_frag(fragbase + (is_pe ? 2 : 3) * 8192, sh_Whi, tid);
    __syncthreads();

    float a2[8][4];
    #pragma unroll
    for (int nt = 0; nt < 8; nt++) {
        a2[nt][0] = 0.f; a2[nt][1] = 0.f; a2[nt][2] = 0.f; a2[nt][3] = 0.f;
    }
    #pragma unroll 2
    for (int kt = 0; kt < 8; kt++) {
        const float* tk = sh_inT + (8 * kt + tig) * 132 + m0 + gid;
        float a0f = tk[0],       a1f = tk[8];
        float a2f = tk[4 * 132], a3f = tk[4 * 132 + 8];
        uint32_t ah0 = f2tf32(a0f), ah1 = f2tf32(a1f);
        uint32_t ah2 = f2tf32(a2f), ah3 = f2tf32(a3f);
        uint32_t al0 = f2tf32(a0f - __uint_as_float(ah0));
        uint32_t al1 = f2tf32(a1f - __uint_as_float(ah1));
        uint32_t al2 = f2tf32(a2f - __uint_as_float(ah2));
        uint32_t al3 = f2tf32(a3f - __uint_as_float(ah3));
        #pragma unroll
        for (int nt = 0; nt < 8; nt++) {
            int fo = ((kt * 8 + nt) * 32 + lane) * 2;
            float2 bh = *(const float2*)(sh_Whi + fo);
            float2 bl = *(const float2*)(sh_Wlo + fo);
            uint32_t bh0 = __float_as_uint(bh.x), bh1 = __float_as_uint(bh.y);
            uint32_t bl0 = __float_as_uint(bl.x), bl1 = __float_as_uint(bl.y);
            mma_tf32(a2[nt], ah0, ah1, ah2, ah3, bh0, bh1);
            mma_tf32(a2[nt], ah0, ah1, ah2, ah3, bl0, bl1);
            mma_tf32(a2[nt], al0, al1, al2, al3, bh0, bh1);
        }
    }

    float* obase = out + (is_pe ? (size_t)N * 64 : 0);
    int g0 = nb + m0 + gid, g1 = g0 + 8;
    #pragma unroll
    for (int nt = 0; nt < 8; nt++) {
        int c = 8 * nt + 2 * tig;
        float b0 = sh_b2[c], b1 = sh_b2[c + 1];
        if (g0 < N) {
            float o0 = a2[nt][0] + b0, o1 = a2[nt][1] + b1;
            if (is_pe) { o0 = tanh_f(o0); o1 = tanh_f(o1); }
            *(float2*)(obase + (size_t)g0 * 64 + c) = make_float2(o0, o1);
        }
        if (g1 < N) {
            float o0 = a2[nt][2] + b0, o1 = a2[nt][3] + b1;
            if (is_pe) { o0 = tanh_f(o0); o1 = tanh_f(o1); }
            *(float2*)(obase + (size_t)g1 * 64 + c) = make_float2(o0, o1);
        }
    }
}

// ============================================================
// Host launch
// ============================================================
extern "C" void kernel_launch(void* const* d_in, const int* in_sizes, int n_in,
                              void* d_out, int out_size)
{
    const float* x       = (const float*)d_in[0];
    const float* pos     = (const float*)d_in[1];
    const float* pe      = (const float*)d_in[2];
    const int*   ei      = (const int*)d_in[3];
    const float* msg_w1  = (const float*)d_in[4];
    const float* msg_b1  = (const float*)d_in[5];
    const float* msg_w2  = (const float*)d_in[6];
    const float* msg_b2  = (const float*)d_in[7];
    const float* mpos_w1 = (const float*)d_in[8];
    const float* mpos_b1 = (const float*)d_in[9];
    const float* mpos_w2 = (const float*)d_in[10];
    const float* mpos_b2 = (const float*)d_in[11];
    const float* upd_w1  = (const float*)d_in[12];
    const float* upd_b1  = (const float*)d_in[13];
    const float* upd_w2  = (const float*)d_in[14];
    const float* upd_b2  = (const float*)d_in[15];
    const float* upe_w1  = (const float*)d_in[16];
    const float* upe_b1  = (const float*)d_in[17];
    const float* upe_w2  = (const float*)d_in[18];
    const float* upe_b2  = (const float*)d_in[19];

    int N = in_sizes[0] / 64;
    int E = in_sizes[3] / 2;

    const int SMEM_PRE  = (64 * 132 + 4096 + 4096 + 128) * 4;              // 67,072 B
    const int SMEM_EDGE = (64 * 132 + 4096 + 4096 + 256) * 4 + 512;        // 68,096 B
    const int SMEM_UPD  = (64 * 132 + 4096 + 4096 + 128) * 4;              // 67,072 B

    cudaFuncSetAttribute(pre_kernel,  cudaFuncAttributeMaxDynamicSharedMemorySize, SMEM_PRE);
    cudaFuncSetAttribute(edge_kernel, cudaFuncAttributeMaxDynamicSharedMemorySize, SMEM_EDGE);
    cudaFuncSetAttribute(upd_kernel,  cudaFuncAttributeMaxDynamicSharedMemorySize, SMEM_UPD);

    dim3 gpre((N + 127) / 128, 2);
    dim3 gupd((N + 127) / 128, 2);
    wfrag_kernel<<<15, 256>>>(msg_w1, msg_w2, mpos_w1, mpos_w2,
                              upd_w1, upd_w2, upe_w1, upe_w2);
    pre_kernel<<<gpre, 256, SMEM_PRE>>>(x, pe, msg_b1, mpos_b1, N);
    edge_kernel<<<(E + 127) / 128, 256, SMEM_EDGE>>>(pos, ei, msg_w1, msg_b2,
                                                     mpos_w1, mpos_b2, E);
    upd_kernel<<<gupd, 256, SMEM_UPD>>>(x, pe, upd_b1, upd_b2, upe_b1, upe_b2,
                                        (float*)d_out, N);
}